// round 1
// baseline (speedup 1.0000x reference)
#include <cuda_runtime.h>
#include <cuda_bf16.h>
#include <cstdint>

// Problem constants
#define BATCH 4
#define SEQ   2048
#define DMODEL 2048
#define NHEAD 16
#define HDIM  128
#define MROWS (BATCH * SEQ)   // 8192

// ---------------------------------------------------------------------------
// Scratch (device globals; allocation in kernel_launch is forbidden)
// ---------------------------------------------------------------------------
__device__ float g_Q[(size_t)MROWS * DMODEL];
__device__ float g_K[(size_t)MROWS * DMODEL];
__device__ float g_V[(size_t)MROWS * DMODEL];
__device__ float g_C[(size_t)MROWS * DMODEL];

// ---------------------------------------------------------------------------
// f32x2 packed-math helpers (Blackwell sm_100+; ptxas never auto-fuses these)
// ---------------------------------------------------------------------------
__device__ __forceinline__ void fma2(unsigned long long& d,
                                     unsigned long long a,
                                     unsigned long long b) {
    asm("fma.rn.f32x2 %0, %1, %2, %0;" : "+l"(d) : "l"(a), "l"(b));
}
__device__ __forceinline__ void mul2ip(unsigned long long& d, unsigned long long a) {
    asm("mul.rn.f32x2 %0, %0, %1;" : "+l"(d) : "l"(a));
}
__device__ __forceinline__ unsigned long long bcast2(float x) {
    unsigned long long r;
    asm("mov.b64 %0, {%1, %1};" : "=l"(r) : "f"(x));
    return r;
}
__device__ __forceinline__ float2 unpack2(unsigned long long v) {
    float2 f;
    asm("mov.b64 {%0, %1}, %2;" : "=f"(f.x), "=f"(f.y) : "l"(v));
    return f;
}

// ---------------------------------------------------------------------------
// SGEMM:  C[M,N] = A[M,K] @ W[N,K]^T      (fp32, f32x2 inner loop)
// Block tile 128x128, K-chunk 16, 256 threads, 8x8 per thread (row-paired).
// M,N multiples of 128; K multiple of 16 (true for all calls here).
// ---------------------------------------------------------------------------
__global__ void __launch_bounds__(256) sgemm_nt(
    const float* __restrict__ A, const float* __restrict__ W,
    float* __restrict__ C, int M, int N, int K)
{
    constexpr int BK = 16;
    constexpr int LDT = 132;   // padded stride (floats) for both smem tiles
    __shared__ __align__(16) float As[BK][LDT];
    __shared__ __align__(16) float Bs[BK][LDT];

    const int tid = threadIdx.x;
    const int tx = tid & 15;        // 0..15  -> N direction (8 cols each)
    const int ty = tid >> 4;        // 0..15  -> M direction (8 rows each)
    const int m0 = blockIdx.y * 128;
    const int n0 = blockIdx.x * 128;

    // acc[i2][j]: packed pair = rows (ty*8+2*i2, ty*8+2*i2+1), col (tx*8+j)
    unsigned long long acc[4][8];
    #pragma unroll
    for (int i = 0; i < 4; i++)
        #pragma unroll
        for (int j = 0; j < 8; j++) acc[i][j] = 0ULL;

    const float* Aptr = A + (size_t)m0 * K;
    const float* Wptr = W + (size_t)n0 * K;

    for (int k0 = 0; k0 < K; k0 += BK) {
        // Load 128x16 A tile and 128x16 W tile (transposed into smem[k][m]).
        #pragma unroll
        for (int i = 0; i < 2; i++) {
            int v   = i * 256 + tid;       // 0..511  (512 float4 per tile)
            int row = v >> 2;              // 0..127
            int c4  = (v & 3) * 4;         // 0,4,8,12
            float4 a = *(const float4*)(Aptr + (size_t)row * K + k0 + c4);
            As[c4 + 0][row] = a.x; As[c4 + 1][row] = a.y;
            As[c4 + 2][row] = a.z; As[c4 + 3][row] = a.w;
            float4 b = *(const float4*)(Wptr + (size_t)row * K + k0 + c4);
            Bs[c4 + 0][row] = b.x; Bs[c4 + 1][row] = b.y;
            Bs[c4 + 2][row] = b.z; Bs[c4 + 3][row] = b.w;
        }
        __syncthreads();

        #pragma unroll
        for (int kk = 0; kk < BK; kk++) {
            unsigned long long a2[4];
            #pragma unroll
            for (int i2 = 0; i2 < 4; i2++)
                a2[i2] = *(const unsigned long long*)&As[kk][ty * 8 + 2 * i2];
            float bf[8];
            *(float4*)(bf)     = *(const float4*)&Bs[kk][tx * 8];
            *(float4*)(bf + 4) = *(const float4*)&Bs[kk][tx * 8 + 4];
            #pragma unroll
            for (int j = 0; j < 8; j++) {
                unsigned long long b2 = bcast2(bf[j]);
                #pragma unroll
                for (int i2 = 0; i2 < 4; i2++) fma2(acc[i2][j], a2[i2], b2);
            }
        }
        __syncthreads();
    }

    // Store 8x8 per thread (two rows per acc pair)
    #pragma unroll
    for (int i2 = 0; i2 < 4; i2++) {
        float lo[8], hi[8];
        #pragma unroll
        for (int j = 0; j < 8; j++) {
            float2 v = unpack2(acc[i2][j]);
            lo[j] = v.x; hi[j] = v.y;
        }
        float* c0 = C + (size_t)(m0 + ty * 8 + 2 * i2) * N + n0 + tx * 8;
        *(float4*)(c0)         = *(float4*)(lo);
        *(float4*)(c0 + 4)     = *(float4*)(lo + 4);
        *(float4*)(c0 + N)     = *(float4*)(hi);
        *(float4*)(c0 + N + 4) = *(float4*)(hi + 4);
    }
}

// ---------------------------------------------------------------------------
// Flash attention (fp32, causal, key padding mask).
// Block = (qtile, head, batch). BQ = BKV = 64, HD = 128, 256 threads.
// Streaming softmax matching the reference's -10000 masking (exp underflows
// to exactly 0 in fp32, identical to jax softmax of -10000 entries).
// ---------------------------------------------------------------------------
__global__ void __launch_bounds__(256) flash_kernel(
    const float* __restrict__ Qg, const float* __restrict__ Kg,
    const float* __restrict__ Vg, const int* __restrict__ amask,
    float* __restrict__ Ctx)
{
    extern __shared__ float smf[];
    float* Qs = smf;                  // [64][128]
    float* Ks = Qs + 64 * 128;        // [64][132]  (padded)
    float* Vs = Ks + 64 * 132;        // [64][128]
    float* Ss = Vs + 64 * 128;        // [64][64]

    const int b  = blockIdx.z;
    const int h  = blockIdx.y;
    const int qt = (int)gridDim.x - 1 - (int)blockIdx.x;  // heavy tiles first
    const int tid = threadIdx.x;
    const int tx = tid & 15, ty = tid >> 4;   // S-tile compute layout
    const int orow = tid >> 2;                // O layout: 1 row / thread-team
    const int oq   = tid & 3;
    const int oc0  = oq * 32;                 // 32-col strip of O per thread

    const size_t base_q = ((size_t)b * SEQ + (size_t)qt * 64) * DMODEL + h * HDIM;

    // Load Q tile
    #pragma unroll
    for (int i = tid; i < 64 * 32; i += 256) {
        int r = i >> 5, c = (i & 31) * 4;
        *(float4*)&Qs[r * 128 + c] =
            *(const float4*)&Qg[base_q + (size_t)r * DMODEL + c];
    }

    unsigned long long o2[16];
    #pragma unroll
    for (int c = 0; c < 16; c++) o2[c] = 0ULL;
    float m_r = -1e30f, l_r = 0.0f;
    const float scale = 0.08838834764831843f;   // 1/sqrt(128)

    for (int kt = 0; kt <= qt; kt++) {
        __syncthreads();   // protects Ks/Vs/Ss reuse + first-iter Qs visibility
        const size_t base_k =
            ((size_t)b * SEQ + (size_t)kt * 64) * DMODEL + h * HDIM;
        #pragma unroll
        for (int i = tid; i < 64 * 32; i += 256) {
            int r = i >> 5, c = (i & 31) * 4;
            *(float4*)&Ks[r * 132 + c] =
                *(const float4*)&Kg[base_k + (size_t)r * DMODEL + c];
            *(float4*)&Vs[r * 128 + c] =
                *(const float4*)&Vg[base_k + (size_t)r * DMODEL + c];
        }
        __syncthreads();

        // S = Q K^T : thread computes rows ty*4+i, cols tx+16*j
        unsigned long long s2[4][4];
        #pragma unroll
        for (int i = 0; i < 4; i++)
            #pragma unroll
            for (int j = 0; j < 4; j++) s2[i][j] = 0ULL;

        #pragma unroll 4
        for (int d = 0; d < 128; d += 2) {
            unsigned long long q2[4], k2[4];
            #pragma unroll
            for (int i = 0; i < 4; i++)
                q2[i] = *(const unsigned long long*)&Qs[(ty * 4 + i) * 128 + d];
            #pragma unroll
            for (int j = 0; j < 4; j++)
                k2[j] = *(const unsigned long long*)&Ks[(tx + 16 * j) * 132 + d];
            #pragma unroll
            for (int i = 0; i < 4; i++)
                #pragma unroll
                for (int j = 0; j < 4; j++) fma2(s2[i][j], q2[i], k2[j]);
        }

        // reduce pair, scale, mask, stage to smem
        #pragma unroll
        for (int i = 0; i < 4; i++) {
            int rg = qt * 64 + ty * 4 + i;
            #pragma unroll
            for (int j = 0; j < 4; j++) {
                int jc = tx + 16 * j;
                int jg = kt * 64 + jc;
                float2 v = unpack2(s2[i][j]);
                float s = (v.x + v.y) * scale;
                if (jg > rg || amask[b * SEQ + jg] == 0) s = -10000.0f;
                Ss[(ty * 4 + i) * 64 + jc] = s;
            }
        }
        __syncthreads();

        // streaming softmax: team of 4 threads per row
        float tmax = -1e30f;
        #pragma unroll
        for (int j = 0; j < 16; j++)
            tmax = fmaxf(tmax, Ss[orow * 64 + oq * 16 + j]);
        tmax = fmaxf(tmax, __shfl_xor_sync(0xffffffffu, tmax, 1));
        tmax = fmaxf(tmax, __shfl_xor_sync(0xffffffffu, tmax, 2));
        float m_new = fmaxf(m_r, tmax);
        float alpha = __expf(m_r - m_new);
        float psum = 0.0f;
        #pragma unroll
        for (int j = 0; j < 16; j++) {
            float p = __expf(Ss[orow * 64 + oq * 16 + j] - m_new);
            Ss[orow * 64 + oq * 16 + j] = p;
            psum += p;
        }
        psum += __shfl_xor_sync(0xffffffffu, psum, 1);
        psum += __shfl_xor_sync(0xffffffffu, psum, 2);
        l_r = l_r * alpha + psum;
        m_r = m_new;
        {
            unsigned long long a2 = bcast2(alpha);
            #pragma unroll
            for (int c = 0; c < 16; c++) mul2ip(o2[c], a2);
        }
        __syncthreads();   // all P staged before PV

        // O += P @ V  (thread: row orow, 32-col strip oc0)
        #pragma unroll 4
        for (int j = 0; j < 64; j++) {
            unsigned long long p2 = bcast2(Ss[orow * 64 + j]);
            const unsigned long long* vrow =
                (const unsigned long long*)&Vs[j * 128 + oc0];
            #pragma unroll
            for (int c = 0; c < 16; c++) fma2(o2[c], p2, vrow[c]);
        }
    }

    // normalize + write context (layout [B,S,D], head h at cols h*128..)
    float inv = 1.0f / l_r;
    #pragma unroll
    for (int c = 0; c < 16; c += 2) {
        float2 v0 = unpack2(o2[c]);
        float2 v1 = unpack2(o2[c + 1]);
        float4 w = make_float4(v0.x * inv, v0.y * inv, v1.x * inv, v1.y * inv);
        *(float4*)&Ctx[base_q + (size_t)orow * DMODEL + oc0 + 2 * c] = w;
    }
}

// ---------------------------------------------------------------------------
// Launch: 3 projection GEMMs -> flash attention -> output projection
// ---------------------------------------------------------------------------
extern "C" void kernel_launch(void* const* d_in, const int* in_sizes, int n_in,
                              void* d_out, int out_size)
{
    const float* query = (const float*)d_in[0];
    const float* key   = (const float*)d_in[1];
    const float* value = (const float*)d_in[2];
    const int*   amask = (const int*)  d_in[3];
    const float* Wq    = (const float*)d_in[4];
    const float* Wk    = (const float*)d_in[5];
    const float* Wv    = (const float*)d_in[6];
    const float* Wo    = (const float*)d_in[7];
    float* out = (float*)d_out;

    float *qb, *kb, *vb, *cb;
    cudaGetSymbolAddress((void**)&qb, g_Q);
    cudaGetSymbolAddress((void**)&kb, g_K);
    cudaGetSymbolAddress((void**)&vb, g_V);
    cudaGetSymbolAddress((void**)&cb, g_C);

    dim3 gg(DMODEL / 128, MROWS / 128);   // (16, 64)
    sgemm_nt<<<gg, 256>>>(query, Wq, qb, MROWS, DMODEL, DMODEL);
    sgemm_nt<<<gg, 256>>>(key,   Wk, kb, MROWS, DMODEL, DMODEL);
    sgemm_nt<<<gg, 256>>>(value, Wv, vb, MROWS, DMODEL, DMODEL);

    const int smem = (64 * 128 + 64 * 132 + 64 * 128 + 64 * 64) * 4;  // 115712 B
    cudaFuncSetAttribute(flash_kernel,
                         cudaFuncAttributeMaxDynamicSharedMemorySize, smem);
    flash_kernel<<<dim3(SEQ / 64, NHEAD, BATCH), 256, smem>>>(qb, kb, vb, amask, cb);

    sgemm_nt<<<gg, 256>>>(cb, Wo, out, MROWS, DMODEL, DMODEL);
}

// round 3
// speedup vs baseline: 1.3047x; 1.3047x over previous
#include <cuda_runtime.h>
#include <cuda_bf16.h>
#include <cstdint>

// Problem constants
#define BATCH 4
#define SEQ   2048
#define DMODEL 2048
#define NHEAD 16
#define HDIM  128
#define MROWS (BATCH * SEQ)   // 8192

// ---------------------------------------------------------------------------
// Scratch (device globals; allocation in kernel_launch is forbidden)
// ---------------------------------------------------------------------------
__device__ float g_Q[(size_t)MROWS * DMODEL];
__device__ float g_K[(size_t)MROWS * DMODEL];
__device__ float g_V[(size_t)MROWS * DMODEL];
__device__ float g_C[(size_t)MROWS * DMODEL];
__device__ __nv_bfloat16 g_Ahi[(size_t)MROWS * DMODEL];
__device__ __nv_bfloat16 g_Alo[(size_t)MROWS * DMODEL];
__device__ __nv_bfloat16 g_Whi[(size_t)DMODEL * DMODEL];
__device__ __nv_bfloat16 g_Wlo[(size_t)DMODEL * DMODEL];

// ---------------------------------------------------------------------------
// PTX helpers (sm_80-level only: mma.sync / ldmatrix / cp.async — the
// harness emits compute_100 PTX, so no tcgen05/sm_100a features).
// ---------------------------------------------------------------------------
__device__ __forceinline__ uint32_t smem_u32(const void* p) {
    uint32_t a;
    asm("{ .reg .u64 t; cvta.to.shared.u64 t, %1; cvt.u32.u64 %0, t; }"
        : "=r"(a) : "l"(p));
    return a;
}
__device__ __forceinline__ void ldsm4(uint32_t* r, uint32_t addr) {
    asm volatile("ldmatrix.sync.aligned.m8n8.x4.shared.b16 {%0,%1,%2,%3}, [%4];"
                 : "=r"(r[0]), "=r"(r[1]), "=r"(r[2]), "=r"(r[3]) : "r"(addr));
}
__device__ __forceinline__ void mma_bf16(float* d, const uint32_t* a,
                                         const uint32_t* b) {
    asm volatile(
        "mma.sync.aligned.m16n8k16.row.col.f32.bf16.bf16.f32 "
        "{%0,%1,%2,%3}, {%4,%5,%6,%7}, {%8,%9}, {%0,%1,%2,%3};"
        : "+f"(d[0]), "+f"(d[1]), "+f"(d[2]), "+f"(d[3])
        : "r"(a[0]), "r"(a[1]), "r"(a[2]), "r"(a[3]), "r"(b[0]), "r"(b[1]));
}
__device__ __forceinline__ void cp16(uint32_t dst, const void* src) {
    asm volatile("cp.async.cg.shared.global [%0], [%1], 16;"
                 :: "r"(dst), "l"(src) : "memory");
}
#define CP_COMMIT asm volatile("cp.async.commit_group;" ::: "memory")
#define CP_WAIT0  asm volatile("cp.async.wait_group 0;" ::: "memory")

// ---------------------------------------------------------------------------
// f32x2 packed-math helpers (flash kernel)
// ---------------------------------------------------------------------------
__device__ __forceinline__ void fma2(unsigned long long& d,
                                     unsigned long long a,
                                     unsigned long long b) {
    asm("fma.rn.f32x2 %0, %1, %2, %0;" : "+l"(d) : "l"(a), "l"(b));
}
__device__ __forceinline__ void mul2ip(unsigned long long& d, unsigned long long a) {
    asm("mul.rn.f32x2 %0, %0, %1;" : "+l"(d) : "l"(a));
}
__device__ __forceinline__ unsigned long long bcast2(float x) {
    unsigned long long r;
    asm("mov.b64 %0, {%1, %1};" : "=l"(r) : "f"(x));
    return r;
}
__device__ __forceinline__ float2 unpack2(unsigned long long v) {
    float2 f;
    asm("mov.b64 {%0, %1}, %2;" : "=f"(f.x), "=f"(f.y) : "l"(v));
    return f;
}

// ---------------------------------------------------------------------------
// Split fp32 -> (hi, lo) bf16 pair.  lo = bf16(x - float(hi)).
// ---------------------------------------------------------------------------
__global__ void __launch_bounds__(256) split_bf16(
    const float* __restrict__ x, __nv_bfloat16* __restrict__ hi,
    __nv_bfloat16* __restrict__ lo, int n4)
{
    int i = blockIdx.x * 256 + threadIdx.x;
    if (i >= n4) return;
    float4 v = ((const float4*)x)[i];
    __nv_bfloat16 h0 = __float2bfloat16(v.x);
    __nv_bfloat16 h1 = __float2bfloat16(v.y);
    __nv_bfloat16 h2 = __float2bfloat16(v.z);
    __nv_bfloat16 h3 = __float2bfloat16(v.w);
    __nv_bfloat16 l0 = __float2bfloat16(v.x - __bfloat162float(h0));
    __nv_bfloat16 l1 = __float2bfloat16(v.y - __bfloat162float(h1));
    __nv_bfloat16 l2 = __float2bfloat16(v.z - __bfloat162float(h2));
    __nv_bfloat16 l3 = __float2bfloat16(v.w - __bfloat162float(h3));
    __nv_bfloat162 hp0, hp1, lp0, lp1;
    hp0.x = h0; hp0.y = h1; hp1.x = h2; hp1.y = h3;
    lp0.x = l0; lp0.y = l1; lp1.x = l2; lp1.y = l3;
    ((uint2*)hi)[i] = make_uint2(*(uint32_t*)&hp0, *(uint32_t*)&hp1);
    ((uint2*)lo)[i] = make_uint2(*(uint32_t*)&lp0, *(uint32_t*)&lp1);
}

// ---------------------------------------------------------------------------
// HMMA split-bf16 GEMM:  C[M,N] = A[M,K] @ W[N,K]^T    (fp32 result)
// C = Ahi*Whi + Ahi*Wlo + Alo*Whi.
// CTA 128x128, BK=32, 8 warps (2x4), warp tile 64x32, cp.async double buffer.
// Smem rows padded to 80 B (5*r mod 8 covers all bank-quads -> ldmatrix
// conflict-free).
// ---------------------------------------------------------------------------
#define GT_ROWB   80                           // bytes per smem row
#define GT_TILE   (128 * GT_ROWB)              // 10240 B per tile
#define GT_STAGE  (4 * GT_TILE)                // 40960 B per stage
#define GT_SMEM   (2 * GT_STAGE)               // 81920 B

__device__ __forceinline__ void gemm_load_chunk(
    uint32_t smb, int stage,
    const __nv_bfloat16* __restrict__ Ahi, const __nv_bfloat16* __restrict__ Alo,
    const __nv_bfloat16* __restrict__ Whi, const __nv_bfloat16* __restrict__ Wlo,
    int m0, int n0, int k0, int K, int tid)
{
    const __nv_bfloat16* srcs[4] = {Ahi, Alo, Whi, Wlo};
    #pragma unroll
    for (int t = 0; t < 4; t++) {
        int row0 = (t < 2) ? m0 : n0;
        const __nv_bfloat16* base = srcs[t] + (size_t)row0 * K + k0;
        #pragma unroll
        for (int i = 0; i < 2; i++) {
            int v = i * 256 + tid;          // 0..511
            int r = v >> 2;                 // 0..127
            int c = (v & 3) * 16;           // byte col 0..48
            cp16(smb + stage * GT_STAGE + t * GT_TILE + r * GT_ROWB + c,
                 (const char*)base + (size_t)r * K * 2 + c);
        }
    }
}

__global__ void __launch_bounds__(256) gemm_hmma(
    const __nv_bfloat16* __restrict__ Ahi, const __nv_bfloat16* __restrict__ Alo,
    const __nv_bfloat16* __restrict__ Whi, const __nv_bfloat16* __restrict__ Wlo,
    float* __restrict__ C, int M, int N, int K)
{
    extern __shared__ __align__(128) char sm[];
    const uint32_t smb = smem_u32(sm);
    const int tid  = threadIdx.x;
    const int wid  = tid >> 5;
    const int lane = tid & 31;
    const int wm = wid >> 2;          // 0..1 : rows wm*64
    const int wn = wid & 3;           // 0..3 : cols wn*32
    const int m0 = blockIdx.y * 128;
    const int n0 = blockIdx.x * 128;

    float acc[4][4][4];
    #pragma unroll
    for (int i = 0; i < 4; i++)
        #pragma unroll
        for (int j = 0; j < 4; j++)
            #pragma unroll
            for (int e = 0; e < 4; e++) acc[i][j][e] = 0.0f;

    // ldmatrix source addresses (element/byte offsets within a tile)
    // A: row = wm*64 + mt*16 + (lane&15), colbyte = kk*2 + ((lane>>4)&1)*16
    const int a_row = wm * 64 + (lane & 15);
    const int a_cb  = ((lane >> 4) & 1) * 16;
    // B (x4 over two n8 tiles): row = wn*32 + nt2*16 + (lane&7) + ((lane>>4)<<3)
    //                           colbyte = kk*2 + ((lane>>3)&1)*16
    const int b_row = wn * 32 + (lane & 7) + ((lane >> 4) << 3);
    const int b_cb  = ((lane >> 3) & 1) * 16;

    gemm_load_chunk(smb, 0, Ahi, Alo, Whi, Wlo, m0, n0, 0, K, tid);
    CP_COMMIT;

    const int nchunks = K / 32;
    for (int c = 0; c < nchunks; c++) {
        const int cur = c & 1;
        CP_WAIT0;
        __syncthreads();
        if (c + 1 < nchunks) {
            gemm_load_chunk(smb, cur ^ 1, Ahi, Alo, Whi, Wlo,
                            m0, n0, (c + 1) * 32, K, tid);
            CP_COMMIT;
        }

        const uint32_t st = smb + cur * GT_STAGE;
        #pragma unroll
        for (int kk = 0; kk < 2; kk++) {       // two k16 steps in the chunk
            const int kb = kk * 32;            // byte offset of k16 within row
            uint32_t b_hi[4][2], b_lo[4][2];
            #pragma unroll
            for (int nt2 = 0; nt2 < 2; nt2++) {
                uint32_t r4[4];
                uint32_t baddr = st + 2 * GT_TILE +
                                 (b_row + nt2 * 16) * GT_ROWB + kb + b_cb;
                ldsm4(r4, baddr);
                b_hi[nt2 * 2][0] = r4[0]; b_hi[nt2 * 2][1] = r4[1];
                b_hi[nt2 * 2 + 1][0] = r4[2]; b_hi[nt2 * 2 + 1][1] = r4[3];
                ldsm4(r4, baddr + GT_TILE);    // Wlo tile
                b_lo[nt2 * 2][0] = r4[0]; b_lo[nt2 * 2][1] = r4[1];
                b_lo[nt2 * 2 + 1][0] = r4[2]; b_lo[nt2 * 2 + 1][1] = r4[3];
            }
            #pragma unroll
            for (int mt = 0; mt < 4; mt++) {
                uint32_t a_hi[4], a_lo[4];
                uint32_t aaddr = st + (a_row + mt * 16) * GT_ROWB + kb + a_cb;
                ldsm4(a_hi, aaddr);
                ldsm4(a_lo, aaddr + GT_TILE);
                #pragma unroll
                for (int nt = 0; nt < 4; nt++) {
                    mma_bf16(acc[mt][nt], a_hi, b_hi[nt]);
                    mma_bf16(acc[mt][nt], a_hi, b_lo[nt]);
                    mma_bf16(acc[mt][nt], a_lo, b_hi[nt]);
                }
            }
        }
        __syncthreads();
    }

    // Epilogue: d0,d1 -> row (lane>>2), cols +0,+1 ; d2,d3 -> row+8
    #pragma unroll
    for (int mt = 0; mt < 4; mt++) {
        const int row = m0 + wm * 64 + mt * 16 + (lane >> 2);
        #pragma unroll
        for (int nt = 0; nt < 4; nt++) {
            const int col = n0 + wn * 32 + nt * 8 + (lane & 3) * 2;
            *(float2*)&C[(size_t)row * N + col] =
                make_float2(acc[mt][nt][0], acc[mt][nt][1]);
            *(float2*)&C[(size_t)(row + 8) * N + col] =
                make_float2(acc[mt][nt][2], acc[mt][nt][3]);
        }
    }
}

// ---------------------------------------------------------------------------
// Flash attention (fp32, causal, key padding mask). Unchanged from R1.
// ---------------------------------------------------------------------------
__global__ void __launch_bounds__(256) flash_kernel(
    const float* __restrict__ Qg, const float* __restrict__ Kg,
    const float* __restrict__ Vg, const int* __restrict__ amask,
    float* __restrict__ Ctx)
{
    extern __shared__ float smf[];
    float* Qs = smf;                  // [64][128]
    float* Ks = Qs + 64 * 128;        // [64][132]  (padded)
    float* Vs = Ks + 64 * 132;        // [64][128]
    float* Ss = Vs + 64 * 128;        // [64][64]

    const int b  = blockIdx.z;
    const int h  = blockIdx.y;
    const int qt = (int)gridDim.x - 1 - (int)blockIdx.x;  // heavy tiles first
    const int tid = threadIdx.x;
    const int tx = tid & 15, ty = tid >> 4;
    const int orow = tid >> 2;
    const int oq   = tid & 3;
    const int oc0  = oq * 32;

    const size_t base_q = ((size_t)b * SEQ + (size_t)qt * 64) * DMODEL + h * HDIM;

    #pragma unroll
    for (int i = tid; i < 64 * 32; i += 256) {
        int r = i >> 5, c = (i & 31) * 4;
        *(float4*)&Qs[r * 128 + c] =
            *(const float4*)&Qg[base_q + (size_t)r * DMODEL + c];
    }

    unsigned long long o2[16];
    #pragma unroll
    for (int c = 0; c < 16; c++) o2[c] = 0ULL;
    float m_r = -1e30f, l_r = 0.0f;
    const float scale = 0.08838834764831843f;   // 1/sqrt(128)

    for (int kt = 0; kt <= qt; kt++) {
        __syncthreads();
        const size_t base_k =
            ((size_t)b * SEQ + (size_t)kt * 64) * DMODEL + h * HDIM;
        #pragma unroll
        for (int i = tid; i < 64 * 32; i += 256) {
            int r = i >> 5, c = (i & 31) * 4;
            *(float4*)&Ks[r * 132 + c] =
                *(const float4*)&Kg[base_k + (size_t)r * DMODEL + c];
            *(float4*)&Vs[r * 128 + c] =
                *(const float4*)&Vg[base_k + (size_t)r * DMODEL + c];
        }
        __syncthreads();

        unsigned long long s2[4][4];
        #pragma unroll
        for (int i = 0; i < 4; i++)
            #pragma unroll
            for (int j = 0; j < 4; j++) s2[i][j] = 0ULL;

        #pragma unroll 4
        for (int d = 0; d < 128; d += 2) {
            unsigned long long q2[4], k2[4];
            #pragma unroll
            for (int i = 0; i < 4; i++)
                q2[i] = *(const unsigned long long*)&Qs[(ty * 4 + i) * 128 + d];
            #pragma unroll
            for (int j = 0; j < 4; j++)
                k2[j] = *(const unsigned long long*)&Ks[(tx + 16 * j) * 132 + d];
            #pragma unroll
            for (int i = 0; i < 4; i++)
                #pragma unroll
                for (int j = 0; j < 4; j++) fma2(s2[i][j], q2[i], k2[j]);
        }

        #pragma unroll
        for (int i = 0; i < 4; i++) {
            int rg = qt * 64 + ty * 4 + i;
            #pragma unroll
            for (int j = 0; j < 4; j++) {
                int jc = tx + 16 * j;
                int jg = kt * 64 + jc;
                float2 v = unpack2(s2[i][j]);
                float s = (v.x + v.y) * scale;
                if (jg > rg || amask[b * SEQ + jg] == 0) s = -10000.0f;
                Ss[(ty * 4 + i) * 64 + jc] = s;
            }
        }
        __syncthreads();

        float tmax = -1e30f;
        #pragma unroll
        for (int j = 0; j < 16; j++)
            tmax = fmaxf(tmax, Ss[orow * 64 + oq * 16 + j]);
        tmax = fmaxf(tmax, __shfl_xor_sync(0xffffffffu, tmax, 1));
        tmax = fmaxf(tmax, __shfl_xor_sync(0xffffffffu, tmax, 2));
        float m_new = fmaxf(m_r, tmax);
        float alpha = __expf(m_r - m_new);
        float psum = 0.0f;
        #pragma unroll
        for (int j = 0; j < 16; j++) {
            float p = __expf(Ss[orow * 64 + oq * 16 + j] - m_new);
            Ss[orow * 64 + oq * 16 + j] = p;
            psum += p;
        }
        psum += __shfl_xor_sync(0xffffffffu, psum, 1);
        psum += __shfl_xor_sync(0xffffffffu, psum, 2);
        l_r = l_r * alpha + psum;
        m_r = m_new;
        {
            unsigned long long a2 = bcast2(alpha);
            #pragma unroll
            for (int c = 0; c < 16; c++) mul2ip(o2[c], a2);
        }
        __syncthreads();

        #pragma unroll 4
        for (int j = 0; j < 64; j++) {
            unsigned long long p2 = bcast2(Ss[orow * 64 + j]);
            const unsigned long long* vrow =
                (const unsigned long long*)&Vs[j * 128 + oc0];
            #pragma unroll
            for (int c = 0; c < 16; c++) fma2(o2[c], p2, vrow[c]);
        }
    }

    float inv = 1.0f / l_r;
    #pragma unroll
    for (int c = 0; c < 16; c += 2) {
        float2 v0 = unpack2(o2[c]);
        float2 v1 = unpack2(o2[c + 1]);
        float4 w = make_float4(v0.x * inv, v0.y * inv, v1.x * inv, v1.y * inv);
        *(float4*)&Ctx[base_q + (size_t)orow * DMODEL + oc0 + 2 * c] = w;
    }
}

// ---------------------------------------------------------------------------
// Launch
// ---------------------------------------------------------------------------
extern "C" void kernel_launch(void* const* d_in, const int* in_sizes, int n_in,
                              void* d_out, int out_size)
{
    const float* query = (const float*)d_in[0];
    const float* key   = (const float*)d_in[1];
    const float* value = (const float*)d_in[2];
    const int*   amask = (const int*)  d_in[3];
    const float* Wq    = (const float*)d_in[4];
    const float* Wk    = (const float*)d_in[5];
    const float* Wv    = (const float*)d_in[6];
    const float* Wo    = (const float*)d_in[7];
    float* out = (float*)d_out;

    float *qb, *kb, *vb, *cb;
    __nv_bfloat16 *ahi, *alo, *whi, *wlo;
    cudaGetSymbolAddress((void**)&qb, g_Q);
    cudaGetSymbolAddress((void**)&kb, g_K);
    cudaGetSymbolAddress((void**)&vb, g_V);
    cudaGetSymbolAddress((void**)&cb, g_C);
    cudaGetSymbolAddress((void**)&ahi, g_Ahi);
    cudaGetSymbolAddress((void**)&alo, g_Alo);
    cudaGetSymbolAddress((void**)&whi, g_Whi);
    cudaGetSymbolAddress((void**)&wlo, g_Wlo);

    cudaFuncSetAttribute(gemm_hmma,
                         cudaFuncAttributeMaxDynamicSharedMemorySize, GT_SMEM);
    const int flash_smem = (64 * 128 + 64 * 132 + 64 * 128 + 64 * 64) * 4;
    cudaFuncSetAttribute(flash_kernel,
                         cudaFuncAttributeMaxDynamicSharedMemorySize, flash_smem);

    const int nA4 = MROWS * DMODEL / 4;
    const int nW4 = DMODEL * DMODEL / 4;
    dim3 gg(DMODEL / 128, MROWS / 128);      // (16, 64)

    // Q = query @ Wq^T
    split_bf16<<<nA4 / 256, 256>>>(query, ahi, alo, nA4);
    split_bf16<<<nW4 / 256, 256>>>(Wq, whi, wlo, nW4);
    gemm_hmma<<<gg, 256, GT_SMEM>>>(ahi, alo, whi, wlo, qb, MROWS, DMODEL, DMODEL);
    // K = key @ Wk^T
    split_bf16<<<nA4 / 256, 256>>>(key, ahi, alo, nA4);
    split_bf16<<<nW4 / 256, 256>>>(Wk, whi, wlo, nW4);
    gemm_hmma<<<gg, 256, GT_SMEM>>>(ahi, alo, whi, wlo, kb, MROWS, DMODEL, DMODEL);
    // V = value @ Wv^T
    split_bf16<<<nA4 / 256, 256>>>(value, ahi, alo, nA4);
    split_bf16<<<nW4 / 256, 256>>>(Wv, whi, wlo, nW4);
    gemm_hmma<<<gg, 256, GT_SMEM>>>(ahi, alo, whi, wlo, vb, MROWS, DMODEL, DMODEL);

    // attention
    flash_kernel<<<dim3(SEQ / 64, NHEAD, BATCH), 256, flash_smem>>>(qb, kb, vb, amask, cb);

    // out = ctx @ Wo^T
    split_bf16<<<nA4 / 256, 256>>>(cb, ahi, alo, nA4);
    split_bf16<<<nW4 / 256, 256>>>(Wo, whi, wlo, nW4);
    gemm_hmma<<<gg, 256, GT_SMEM>>>(ahi, alo, whi, wlo, out, MROWS, DMODEL, DMODEL);
}

// round 4
// speedup vs baseline: 5.2281x; 4.0072x over previous
#include <cuda_runtime.h>
#include <cuda_bf16.h>
#include <cstdint>

// Problem constants
#define BATCH 4
#define SEQ   2048
#define DMODEL 2048
#define NHEAD 16
#define HDIM  128
#define MROWS (BATCH * SEQ)   // 8192

// ---------------------------------------------------------------------------
// Scratch (device globals; allocation in kernel_launch is forbidden)
// ---------------------------------------------------------------------------
__device__ __nv_bfloat16 g_Ahi[(size_t)MROWS * DMODEL];
__device__ __nv_bfloat16 g_Alo[(size_t)MROWS * DMODEL];
__device__ __nv_bfloat16 g_Whi[(size_t)DMODEL * DMODEL];
__device__ __nv_bfloat16 g_Wlo[(size_t)DMODEL * DMODEL];
__device__ __nv_bfloat16 g_QHi[(size_t)MROWS * DMODEL];
__device__ __nv_bfloat16 g_QLo[(size_t)MROWS * DMODEL];
__device__ __nv_bfloat16 g_KHi[(size_t)MROWS * DMODEL];
__device__ __nv_bfloat16 g_KLo[(size_t)MROWS * DMODEL];
__device__ __nv_bfloat16 g_VHi[(size_t)MROWS * DMODEL];
__device__ __nv_bfloat16 g_VLo[(size_t)MROWS * DMODEL];
__device__ __nv_bfloat16 g_CHi[(size_t)MROWS * DMODEL];
__device__ __nv_bfloat16 g_CLo[(size_t)MROWS * DMODEL];

// ---------------------------------------------------------------------------
// PTX helpers (sm_80-level: mma.sync / ldmatrix / cp.async; the harness emits
// compute_100 PTX so no tcgen05/sm_100a features are available).
// ---------------------------------------------------------------------------
__device__ __forceinline__ uint32_t smem_u32(const void* p) {
    uint32_t a;
    asm("{ .reg .u64 t; cvta.to.shared.u64 t, %1; cvt.u32.u64 %0, t; }"
        : "=r"(a) : "l"(p));
    return a;
}
__device__ __forceinline__ void ldsm4(uint32_t* r, uint32_t addr) {
    asm volatile("ldmatrix.sync.aligned.m8n8.x4.shared.b16 {%0,%1,%2,%3}, [%4];"
                 : "=r"(r[0]), "=r"(r[1]), "=r"(r[2]), "=r"(r[3]) : "r"(addr));
}
__device__ __forceinline__ void ldsm4t(uint32_t* r, uint32_t addr) {
    asm volatile("ldmatrix.sync.aligned.m8n8.x4.trans.shared.b16 {%0,%1,%2,%3}, [%4];"
                 : "=r"(r[0]), "=r"(r[1]), "=r"(r[2]), "=r"(r[3]) : "r"(addr));
}
__device__ __forceinline__ void mma_bf16(float* d, const uint32_t* a,
                                         const uint32_t* b) {
    asm volatile(
        "mma.sync.aligned.m16n8k16.row.col.f32.bf16.bf16.f32 "
        "{%0,%1,%2,%3}, {%4,%5,%6,%7}, {%8,%9}, {%0,%1,%2,%3};"
        : "+f"(d[0]), "+f"(d[1]), "+f"(d[2]), "+f"(d[3])
        : "r"(a[0]), "r"(a[1]), "r"(a[2]), "r"(a[3]), "r"(b[0]), "r"(b[1]));
}
__device__ __forceinline__ void cp16(uint32_t dst, const void* src) {
    asm volatile("cp.async.cg.shared.global [%0], [%1], 16;"
                 :: "r"(dst), "l"(src) : "memory");
}
#define CP_COMMIT asm volatile("cp.async.commit_group;" ::: "memory")
#define CP_WAIT0  asm volatile("cp.async.wait_group 0;" ::: "memory")

// pack two fp32 -> bf16x2 (lo in low half, hi in high half)
__device__ __forceinline__ uint32_t pack_bf16x2(float lo, float hi) {
    uint32_t r;
    asm("cvt.rn.bf16x2.f32 %0, %1, %2;" : "=r"(r) : "f"(hi), "f"(lo));
    return r;
}
__device__ __forceinline__ float2 bf16x2_f2(uint32_t u) {
    __nv_bfloat162 h = *reinterpret_cast<__nv_bfloat162*>(&u);
    return __bfloat1622float2(h);
}

// ---------------------------------------------------------------------------
// Split fp32 -> (hi, lo) bf16 pair.  lo = bf16(x - float(hi)).
// ---------------------------------------------------------------------------
__global__ void __launch_bounds__(256) split_bf16(
    const float* __restrict__ x, __nv_bfloat16* __restrict__ hi,
    __nv_bfloat16* __restrict__ lo, int n4)
{
    int i = blockIdx.x * 256 + threadIdx.x;
    if (i >= n4) return;
    float4 v = ((const float4*)x)[i];
    uint32_t h0 = pack_bf16x2(v.x, v.y);
    uint32_t h1 = pack_bf16x2(v.z, v.w);
    float2 f0 = bf16x2_f2(h0), f1 = bf16x2_f2(h1);
    uint32_t l0 = pack_bf16x2(v.x - f0.x, v.y - f0.y);
    uint32_t l1 = pack_bf16x2(v.z - f1.x, v.w - f1.y);
    ((uint2*)hi)[i] = make_uint2(h0, h1);
    ((uint2*)lo)[i] = make_uint2(l0, l1);
}

// ---------------------------------------------------------------------------
// HMMA split-bf16 GEMM:  C[M,N] = A[M,K] @ W[N,K]^T
// C = Ahi*Whi + Ahi*Wlo + Alo*Whi.
// CTA 128x128, BK=32, 8 warps (2x4), warp tile 64x32, cp.async double buffer.
// EPI=0: store fp32 C.   EPI=1: store split bf16 (Chi, Clo).
// ---------------------------------------------------------------------------
#define GT_ROWB   80
#define GT_TILE   (128 * GT_ROWB)
#define GT_STAGE  (4 * GT_TILE)
#define GT_SMEM   (2 * GT_STAGE)               // 81920 B

__device__ __forceinline__ void gemm_load_chunk(
    uint32_t smb, int stage,
    const __nv_bfloat16* __restrict__ Ahi, const __nv_bfloat16* __restrict__ Alo,
    const __nv_bfloat16* __restrict__ Whi, const __nv_bfloat16* __restrict__ Wlo,
    int m0, int n0, int k0, int K, int tid)
{
    const __nv_bfloat16* srcs[4] = {Ahi, Alo, Whi, Wlo};
    #pragma unroll
    for (int t = 0; t < 4; t++) {
        int row0 = (t < 2) ? m0 : n0;
        const __nv_bfloat16* base = srcs[t] + (size_t)row0 * K + k0;
        #pragma unroll
        for (int i = 0; i < 2; i++) {
            int v = i * 256 + tid;
            int r = v >> 2;
            int c = (v & 3) * 16;
            cp16(smb + stage * GT_STAGE + t * GT_TILE + r * GT_ROWB + c,
                 (const char*)base + (size_t)r * K * 2 + c);
        }
    }
}

template <int EPI>
__global__ void __launch_bounds__(256) gemm_hmma(
    const __nv_bfloat16* __restrict__ Ahi, const __nv_bfloat16* __restrict__ Alo,
    const __nv_bfloat16* __restrict__ Whi, const __nv_bfloat16* __restrict__ Wlo,
    float* __restrict__ C, __nv_bfloat16* __restrict__ Chi,
    __nv_bfloat16* __restrict__ Clo, int M, int N, int K)
{
    extern __shared__ __align__(128) char sm[];
    const uint32_t smb = smem_u32(sm);
    const int tid  = threadIdx.x;
    const int wid  = tid >> 5;
    const int lane = tid & 31;
    const int wm = wid >> 2;
    const int wn = wid & 3;
    const int m0 = blockIdx.y * 128;
    const int n0 = blockIdx.x * 128;

    float acc[4][4][4];
    #pragma unroll
    for (int i = 0; i < 4; i++)
        #pragma unroll
        for (int j = 0; j < 4; j++)
            #pragma unroll
            for (int e = 0; e < 4; e++) acc[i][j][e] = 0.0f;

    const int a_row = wm * 64 + (lane & 15);
    const int a_cb  = ((lane >> 4) & 1) * 16;
    const int b_row = wn * 32 + (lane & 7) + ((lane >> 4) << 3);
    const int b_cb  = ((lane >> 3) & 1) * 16;

    gemm_load_chunk(smb, 0, Ahi, Alo, Whi, Wlo, m0, n0, 0, K, tid);
    CP_COMMIT;

    const int nchunks = K / 32;
    for (int c = 0; c < nchunks; c++) {
        const int cur = c & 1;
        CP_WAIT0;
        __syncthreads();
        if (c + 1 < nchunks) {
            gemm_load_chunk(smb, cur ^ 1, Ahi, Alo, Whi, Wlo,
                            m0, n0, (c + 1) * 32, K, tid);
            CP_COMMIT;
        }

        const uint32_t st = smb + cur * GT_STAGE;
        #pragma unroll
        for (int kk = 0; kk < 2; kk++) {
            const int kb = kk * 32;
            uint32_t b_hi[4][2], b_lo[4][2];
            #pragma unroll
            for (int nt2 = 0; nt2 < 2; nt2++) {
                uint32_t r4[4];
                uint32_t baddr = st + 2 * GT_TILE +
                                 (b_row + nt2 * 16) * GT_ROWB + kb + b_cb;
                ldsm4(r4, baddr);
                b_hi[nt2 * 2][0] = r4[0]; b_hi[nt2 * 2][1] = r4[1];
                b_hi[nt2 * 2 + 1][0] = r4[2]; b_hi[nt2 * 2 + 1][1] = r4[3];
                ldsm4(r4, baddr + GT_TILE);
                b_lo[nt2 * 2][0] = r4[0]; b_lo[nt2 * 2][1] = r4[1];
                b_lo[nt2 * 2 + 1][0] = r4[2]; b_lo[nt2 * 2 + 1][1] = r4[3];
            }
            #pragma unroll
            for (int mt = 0; mt < 4; mt++) {
                uint32_t a_hi[4], a_lo[4];
                uint32_t aaddr = st + (a_row + mt * 16) * GT_ROWB + kb + a_cb;
                ldsm4(a_hi, aaddr);
                ldsm4(a_lo, aaddr + GT_TILE);
                #pragma unroll
                for (int nt = 0; nt < 4; nt++) {
                    mma_bf16(acc[mt][nt], a_hi, b_hi[nt]);
                    mma_bf16(acc[mt][nt], a_hi, b_lo[nt]);
                    mma_bf16(acc[mt][nt], a_lo, b_hi[nt]);
                }
            }
        }
        __syncthreads();
    }

    #pragma unroll
    for (int mt = 0; mt < 4; mt++) {
        const int row = m0 + wm * 64 + mt * 16 + (lane >> 2);
        #pragma unroll
        for (int nt = 0; nt < 4; nt++) {
            const int col = n0 + wn * 32 + nt * 8 + (lane & 3) * 2;
            if (EPI == 0) {
                *(float2*)&C[(size_t)row * N + col] =
                    make_float2(acc[mt][nt][0], acc[mt][nt][1]);
                *(float2*)&C[(size_t)(row + 8) * N + col] =
                    make_float2(acc[mt][nt][2], acc[mt][nt][3]);
            } else {
                uint32_t h0 = pack_bf16x2(acc[mt][nt][0], acc[mt][nt][1]);
                float2 f0 = bf16x2_f2(h0);
                uint32_t l0 = pack_bf16x2(acc[mt][nt][0] - f0.x,
                                          acc[mt][nt][1] - f0.y);
                *(uint32_t*)&Chi[(size_t)row * N + col] = h0;
                *(uint32_t*)&Clo[(size_t)row * N + col] = l0;
                uint32_t h1 = pack_bf16x2(acc[mt][nt][2], acc[mt][nt][3]);
                float2 f1 = bf16x2_f2(h1);
                uint32_t l1 = pack_bf16x2(acc[mt][nt][2] - f1.x,
                                          acc[mt][nt][3] - f1.y);
                *(uint32_t*)&Chi[(size_t)(row + 8) * N + col] = h1;
                *(uint32_t*)&Clo[(size_t)(row + 8) * N + col] = l1;
            }
        }
    }
}

// ---------------------------------------------------------------------------
// Flash attention with HMMA (split-bf16 QK^T and PV, fp32 softmax).
// BQ=128, BKV=64, HD=128. 8 warps; warp w owns Q rows [w*16, w*16+16).
// Smem rows padded to 272 B (16B-aligned, conflict-free ldmatrix).
// ---------------------------------------------------------------------------
#define FS_ROWB 272
#define FS_QHI  0
#define FS_QLO  (128 * FS_ROWB)           // 34816
#define FS_KHI  (2 * 128 * FS_ROWB)       // 69632
#define FS_KLO  (FS_KHI + 64 * FS_ROWB)   // 87040
#define FS_VHI  (FS_KHI + 2 * 64 * FS_ROWB)
#define FS_VLO  (FS_KHI + 3 * 64 * FS_ROWB)
#define FS_MSK  (FS_KHI + 4 * 64 * FS_ROWB)   // 139264
#define FS_SMEM (FS_MSK + 256)                // 139520

__global__ void __launch_bounds__(256) flash_hmma(
    const __nv_bfloat16* __restrict__ qhi, const __nv_bfloat16* __restrict__ qlo,
    const __nv_bfloat16* __restrict__ khi, const __nv_bfloat16* __restrict__ klo,
    const __nv_bfloat16* __restrict__ vhi, const __nv_bfloat16* __restrict__ vlo,
    const int* __restrict__ amask,
    __nv_bfloat16* __restrict__ chi, __nv_bfloat16* __restrict__ clo)
{
    extern __shared__ __align__(128) char sm[];
    const uint32_t smb = smem_u32(sm);
    int* Ms = (int*)(sm + FS_MSK);

    const int b  = blockIdx.z;
    const int h  = blockIdx.y;
    const int qt = (int)gridDim.x - 1 - (int)blockIdx.x;   // heavy tiles first
    const int tid = threadIdx.x;
    const int wid = tid >> 5;
    const int lane = tid & 31;

    const size_t qrow0 = (size_t)b * SEQ + (size_t)qt * 128;

    // Q tile -> smem (hi + lo), once per block
    #pragma unroll
    for (int i = 0; i < 8; i++) {
        int idx = i * 256 + tid;
        int r = idx >> 4;
        int c = (idx & 15) * 16;
        size_t go = ((qrow0 + r) * DMODEL + h * HDIM) * 2 + c;
        cp16(smb + FS_QHI + r * FS_ROWB + c, (const char*)qhi + go);
        cp16(smb + FS_QLO + r * FS_ROWB + c, (const char*)qlo + go);
    }
    CP_COMMIT;

    float o[16][4];
    #pragma unroll
    for (int nt = 0; nt < 16; nt++)
        #pragma unroll
        for (int e = 0; e < 4; e++) o[nt][e] = 0.0f;
    float mA = -1e30f, mB = -1e30f, lA = 0.0f, lB = 0.0f;

    const float scale = 0.08838834764831843f;   // 1/sqrt(128)
    const int rA = lane >> 2;
    const int growA = qt * 128 + wid * 16 + rA;
    const int growB = growA + 8;
    const int ktmax = 2 * qt + 1;

    for (int kt = 0; kt <= ktmax; kt++) {
        __syncthreads();   // previous PV done reading Vs / Ms
        const size_t krow0 = (size_t)b * SEQ + (size_t)kt * 64;
        #pragma unroll
        for (int i = 0; i < 4; i++) {
            int idx = i * 256 + tid;
            int r = idx >> 4;
            int c = (idx & 15) * 16;
            size_t go = ((krow0 + r) * DMODEL + h * HDIM) * 2 + c;
            cp16(smb + FS_KHI + r * FS_ROWB + c, (const char*)khi + go);
            cp16(smb + FS_KLO + r * FS_ROWB + c, (const char*)klo + go);
            cp16(smb + FS_VHI + r * FS_ROWB + c, (const char*)vhi + go);
            cp16(smb + FS_VLO + r * FS_ROWB + c, (const char*)vlo + go);
        }
        if (tid < 64) Ms[tid] = amask[b * SEQ + kt * 64 + tid];
        CP_COMMIT;
        CP_WAIT0;
        __syncthreads();

        // ---- S = Q K^T (3-way split MMA), warp rows wid*16..+15 ----
        float s[8][4];
        #pragma unroll
        for (int nt = 0; nt < 8; nt++)
            #pragma unroll
            for (int e = 0; e < 4; e++) s[nt][e] = 0.0f;

        #pragma unroll
        for (int kk = 0; kk < 8; kk++) {
            uint32_t qh[4], ql[4];
            uint32_t aaddr = smb + FS_QHI + (wid * 16 + (lane & 15)) * FS_ROWB +
                             kk * 32 + ((lane >> 4) & 1) * 16;
            ldsm4(qh, aaddr);
            ldsm4(ql, aaddr + (FS_QLO - FS_QHI));
            #pragma unroll
            for (int g = 0; g < 4; g++) {
                uint32_t kh[4], kl[4];
                uint32_t baddr = smb + FS_KHI +
                                 (g * 16 + (lane & 7) + ((lane >> 4) << 3)) * FS_ROWB +
                                 kk * 32 + ((lane >> 3) & 1) * 16;
                ldsm4(kh, baddr);
                ldsm4(kl, baddr + (FS_KLO - FS_KHI));
                mma_bf16(s[2 * g], qh, kh);
                mma_bf16(s[2 * g], qh, kl);
                mma_bf16(s[2 * g], ql, kh);
                mma_bf16(s[2 * g + 1], qh, kh + 2);
                mma_bf16(s[2 * g + 1], qh, kl + 2);
                mma_bf16(s[2 * g + 1], ql, kh + 2);
            }
        }

        // ---- mask + scale ----
        float tmaxA = -1e30f, tmaxB = -1e30f;
        #pragma unroll
        for (int nt = 0; nt < 8; nt++) {
            int lc = nt * 8 + (lane & 3) * 2;
            int gc = kt * 64 + lc;
            int mk0 = Ms[lc], mk1 = Ms[lc + 1];
            float v0 = s[nt][0] * scale; if (gc > growA || !mk0) v0 = -10000.0f;
            float v1 = s[nt][1] * scale; if (gc + 1 > growA || !mk1) v1 = -10000.0f;
            float v2 = s[nt][2] * scale; if (gc > growB || !mk0) v2 = -10000.0f;
            float v3 = s[nt][3] * scale; if (gc + 1 > growB || !mk1) v3 = -10000.0f;
            s[nt][0] = v0; s[nt][1] = v1; s[nt][2] = v2; s[nt][3] = v3;
            tmaxA = fmaxf(tmaxA, fmaxf(v0, v1));
            tmaxB = fmaxf(tmaxB, fmaxf(v2, v3));
        }
        tmaxA = fmaxf(tmaxA, __shfl_xor_sync(0xffffffffu, tmaxA, 1));
        tmaxA = fmaxf(tmaxA, __shfl_xor_sync(0xffffffffu, tmaxA, 2));
        tmaxB = fmaxf(tmaxB, __shfl_xor_sync(0xffffffffu, tmaxB, 1));
        tmaxB = fmaxf(tmaxB, __shfl_xor_sync(0xffffffffu, tmaxB, 2));

        float mAn = fmaxf(mA, tmaxA), mBn = fmaxf(mB, tmaxB);
        float aAl = __expf(mA - mAn), aBl = __expf(mB - mBn);

        // ---- P = exp(S - m), split to bf16 hi/lo fragments (in-register) ----
        uint32_t phi[8][2], plo[8][2];
        float sumA = 0.0f, sumB = 0.0f;
        #pragma unroll
        for (int nt = 0; nt < 8; nt++) {
            float p0 = __expf(s[nt][0] - mAn), p1 = __expf(s[nt][1] - mAn);
            float p2 = __expf(s[nt][2] - mBn), p3 = __expf(s[nt][3] - mBn);
            sumA += p0 + p1; sumB += p2 + p3;
            uint32_t hA = pack_bf16x2(p0, p1);
            float2 fA = bf16x2_f2(hA);
            phi[nt][0] = hA;
            plo[nt][0] = pack_bf16x2(p0 - fA.x, p1 - fA.y);
            uint32_t hB = pack_bf16x2(p2, p3);
            float2 fB = bf16x2_f2(hB);
            phi[nt][1] = hB;
            plo[nt][1] = pack_bf16x2(p2 - fB.x, p3 - fB.y);
        }
        sumA += __shfl_xor_sync(0xffffffffu, sumA, 1);
        sumA += __shfl_xor_sync(0xffffffffu, sumA, 2);
        sumB += __shfl_xor_sync(0xffffffffu, sumB, 1);
        sumB += __shfl_xor_sync(0xffffffffu, sumB, 2);
        lA = lA * aAl + sumA;
        lB = lB * aBl + sumB;
        mA = mAn; mB = mBn;

        #pragma unroll
        for (int nt = 0; nt < 16; nt++) {
            o[nt][0] *= aAl; o[nt][1] *= aAl;
            o[nt][2] *= aBl; o[nt][3] *= aBl;
        }

        // ---- O += P @ V (3-way split MMA) ----
        #pragma unroll
        for (int t = 0; t < 4; t++) {
            uint32_t ah[4] = {phi[2 * t][0], phi[2 * t][1],
                              phi[2 * t + 1][0], phi[2 * t + 1][1]};
            uint32_t al[4] = {plo[2 * t][0], plo[2 * t][1],
                              plo[2 * t + 1][0], plo[2 * t + 1][1]};
            #pragma unroll
            for (int g = 0; g < 8; g++) {
                uint32_t vh[4], vl[4];
                uint32_t vaddr = smb + FS_VHI +
                                 (t * 16 + (lane & 7) + ((lane >> 3) & 1) * 8) * FS_ROWB +
                                 g * 32 + (lane >> 4) * 16;
                ldsm4t(vh, vaddr);
                ldsm4t(vl, vaddr + (FS_VLO - FS_VHI));
                mma_bf16(o[2 * g], ah, vh);
                mma_bf16(o[2 * g], al, vh);
                mma_bf16(o[2 * g], ah, vl);
                mma_bf16(o[2 * g + 1], ah, vh + 2);
                mma_bf16(o[2 * g + 1], al, vh + 2);
                mma_bf16(o[2 * g + 1], ah, vl + 2);
            }
        }
    }

    // ---- normalize, split to bf16 hi/lo, store context ----
    const float invA = 1.0f / lA, invB = 1.0f / lB;
    const size_t rgA = qrow0 + wid * 16 + rA;
    const size_t rgB = rgA + 8;
    #pragma unroll
    for (int nt = 0; nt < 16; nt++) {
        int col = h * HDIM + nt * 8 + (lane & 3) * 2;
        float x0 = o[nt][0] * invA, x1 = o[nt][1] * invA;
        uint32_t hA = pack_bf16x2(x0, x1);
        float2 fA = bf16x2_f2(hA);
        *(uint32_t*)&chi[rgA * DMODEL + col] = hA;
        *(uint32_t*)&clo[rgA * DMODEL + col] = pack_bf16x2(x0 - fA.x, x1 - fA.y);
        float x2 = o[nt][2] * invB, x3 = o[nt][3] * invB;
        uint32_t hB = pack_bf16x2(x2, x3);
        float2 fB = bf16x2_f2(hB);
        *(uint32_t*)&chi[rgB * DMODEL + col] = hB;
        *(uint32_t*)&clo[rgB * DMODEL + col] = pack_bf16x2(x2 - fB.x, x3 - fB.y);
    }
}

// ---------------------------------------------------------------------------
// Launch
// ---------------------------------------------------------------------------
extern "C" void kernel_launch(void* const* d_in, const int* in_sizes, int n_in,
                              void* d_out, int out_size)
{
    const float* query = (const float*)d_in[0];
    const float* key   = (const float*)d_in[1];
    const float* value = (const float*)d_in[2];
    const int*   amask = (const int*)  d_in[3];
    const float* Wq    = (const float*)d_in[4];
    const float* Wk    = (const float*)d_in[5];
    const float* Wv    = (const float*)d_in[6];
    const float* Wo    = (const float*)d_in[7];
    float* out = (float*)d_out;

    __nv_bfloat16 *ahi, *alo, *whi, *wlo;
    __nv_bfloat16 *qhi, *qlo, *khi, *klo, *vhi, *vlo, *chi, *clo;
    cudaGetSymbolAddress((void**)&ahi, g_Ahi);
    cudaGetSymbolAddress((void**)&alo, g_Alo);
    cudaGetSymbolAddress((void**)&whi, g_Whi);
    cudaGetSymbolAddress((void**)&wlo, g_Wlo);
    cudaGetSymbolAddress((void**)&qhi, g_QHi);
    cudaGetSymbolAddress((void**)&qlo, g_QLo);
    cudaGetSymbolAddress((void**)&khi, g_KHi);
    cudaGetSymbolAddress((void**)&klo, g_KLo);
    cudaGetSymbolAddress((void**)&vhi, g_VHi);
    cudaGetSymbolAddress((void**)&vlo, g_VLo);
    cudaGetSymbolAddress((void**)&chi, g_CHi);
    cudaGetSymbolAddress((void**)&clo, g_CLo);

    cudaFuncSetAttribute(gemm_hmma<0>,
                         cudaFuncAttributeMaxDynamicSharedMemorySize, GT_SMEM);
    cudaFuncSetAttribute(gemm_hmma<1>,
                         cudaFuncAttributeMaxDynamicSharedMemorySize, GT_SMEM);
    cudaFuncSetAttribute(flash_hmma,
                         cudaFuncAttributeMaxDynamicSharedMemorySize, FS_SMEM);

    const int nA4 = MROWS * DMODEL / 4;
    const int nW4 = DMODEL * DMODEL / 4;
    dim3 gg(DMODEL / 128, MROWS / 128);      // (16, 64)

    // Q = query @ Wq^T  (split-bf16 output)
    split_bf16<<<nA4 / 256, 256>>>(query, ahi, alo, nA4);
    split_bf16<<<nW4 / 256, 256>>>(Wq, whi, wlo, nW4);
    gemm_hmma<1><<<gg, 256, GT_SMEM>>>(ahi, alo, whi, wlo, nullptr, qhi, qlo,
                                       MROWS, DMODEL, DMODEL);
    // K = key @ Wk^T
    split_bf16<<<nA4 / 256, 256>>>(key, ahi, alo, nA4);
    split_bf16<<<nW4 / 256, 256>>>(Wk, whi, wlo, nW4);
    gemm_hmma<1><<<gg, 256, GT_SMEM>>>(ahi, alo, whi, wlo, nullptr, khi, klo,
                                       MROWS, DMODEL, DMODEL);
    // V = value @ Wv^T
    split_bf16<<<nA4 / 256, 256>>>(value, ahi, alo, nA4);
    split_bf16<<<nW4 / 256, 256>>>(Wv, whi, wlo, nW4);
    gemm_hmma<1><<<gg, 256, GT_SMEM>>>(ahi, alo, whi, wlo, nullptr, vhi, vlo,
                                       MROWS, DMODEL, DMODEL);

    // attention (emits split context directly)
    flash_hmma<<<dim3(SEQ / 128, NHEAD, BATCH), 256, FS_SMEM>>>(
        qhi, qlo, khi, klo, vhi, vlo, amask, chi, clo);

    // out = ctx @ Wo^T (fp32 output)
    split_bf16<<<nW4 / 256, 256>>>(Wo, whi, wlo, nW4);
    gemm_hmma<0><<<gg, 256, GT_SMEM>>>(chi, clo, whi, wlo, out, nullptr, nullptr,
                                       MROWS, DMODEL, DMODEL);
}

// round 5
// speedup vs baseline: 7.2348x; 1.3838x over previous
#include <cuda_runtime.h>
#include <cuda_fp16.h>
#include <cstdint>

// Problem constants
#define BATCH 4
#define SEQ   2048
#define DMODEL 2048
#define NHEAD 16
#define HDIM  128
#define MROWS (BATCH * SEQ)   // 8192

// ---------------------------------------------------------------------------
// Scratch (device globals; allocation in kernel_launch is forbidden)
// ---------------------------------------------------------------------------
__device__ __half g_Xq[(size_t)MROWS * DMODEL];   // fp16(query)
__device__ __half g_Xk[(size_t)MROWS * DMODEL];
__device__ __half g_Xv[(size_t)MROWS * DMODEL];
__device__ __half g_Wqh[(size_t)DMODEL * DMODEL];
__device__ __half g_Wql[(size_t)DMODEL * DMODEL];
__device__ __half g_Wkh[(size_t)DMODEL * DMODEL];
__device__ __half g_Wkl[(size_t)DMODEL * DMODEL];
__device__ __half g_Wvh[(size_t)DMODEL * DMODEL];
__device__ __half g_Wvl[(size_t)DMODEL * DMODEL];
__device__ __half g_Woh[(size_t)DMODEL * DMODEL];
__device__ __half g_Wol[(size_t)DMODEL * DMODEL];
__device__ __half g_Qh[(size_t)MROWS * DMODEL];
__device__ __half g_Kh[(size_t)MROWS * DMODEL];
__device__ __half g_Kl[(size_t)MROWS * DMODEL];
__device__ __half g_Vh[(size_t)MROWS * DMODEL];
__device__ __half g_Vl[(size_t)MROWS * DMODEL];
__device__ __half g_Ch[(size_t)MROWS * DMODEL];

// ---------------------------------------------------------------------------
// PTX helpers (sm_80-level: mma.sync / ldmatrix / cp.async)
// ---------------------------------------------------------------------------
__device__ __forceinline__ uint32_t smem_u32(const void* p) {
    uint32_t a;
    asm("{ .reg .u64 t; cvta.to.shared.u64 t, %1; cvt.u32.u64 %0, t; }"
        : "=r"(a) : "l"(p));
    return a;
}
__device__ __forceinline__ void ldsm4(uint32_t* r, uint32_t addr) {
    asm volatile("ldmatrix.sync.aligned.m8n8.x4.shared.b16 {%0,%1,%2,%3}, [%4];"
                 : "=r"(r[0]), "=r"(r[1]), "=r"(r[2]), "=r"(r[3]) : "r"(addr));
}
__device__ __forceinline__ void ldsm4t(uint32_t* r, uint32_t addr) {
    asm volatile("ldmatrix.sync.aligned.m8n8.x4.trans.shared.b16 {%0,%1,%2,%3}, [%4];"
                 : "=r"(r[0]), "=r"(r[1]), "=r"(r[2]), "=r"(r[3]) : "r"(addr));
}
__device__ __forceinline__ void mma_f16(float* d, const uint32_t* a,
                                        const uint32_t* b) {
    asm volatile(
        "mma.sync.aligned.m16n8k16.row.col.f32.f16.f16.f32 "
        "{%0,%1,%2,%3}, {%4,%5,%6,%7}, {%8,%9}, {%0,%1,%2,%3};"
        : "+f"(d[0]), "+f"(d[1]), "+f"(d[2]), "+f"(d[3])
        : "r"(a[0]), "r"(a[1]), "r"(a[2]), "r"(a[3]), "r"(b[0]), "r"(b[1]));
}
__device__ __forceinline__ void cp16(uint32_t dst, const void* src) {
    asm volatile("cp.async.cg.shared.global [%0], [%1], 16;"
                 :: "r"(dst), "l"(src) : "memory");
}
#define CP_COMMIT asm volatile("cp.async.commit_group;" ::: "memory")
#define CP_WAIT0  asm volatile("cp.async.wait_group 0;" ::: "memory")
#define CP_WAIT1  asm volatile("cp.async.wait_group 1;" ::: "memory")

// pack two fp32 -> half2 (first arg -> low half)
__device__ __forceinline__ uint32_t pack_h2(float lo, float hi) {
    uint32_t r;
    asm("cvt.rn.f16x2.f32 %0, %1, %2;" : "=r"(r) : "f"(hi), "f"(lo));
    return r;
}
__device__ __forceinline__ float2 h2_f2(uint32_t u) {
    __half2 h = *reinterpret_cast<__half2*>(&u);
    return __half22float2(h);
}

// ---------------------------------------------------------------------------
// Convert fp32 -> fp16 (activations: hi only)
// ---------------------------------------------------------------------------
__global__ void __launch_bounds__(256) cvt_f16(
    const float* __restrict__ x, __half* __restrict__ h, int n4)
{
    int i = blockIdx.x * 256 + threadIdx.x;
    if (i >= n4) return;
    float4 v = ((const float4*)x)[i];
    ((uint2*)h)[i] = make_uint2(pack_h2(v.x, v.y), pack_h2(v.z, v.w));
}

// Split fp32 -> (hi, lo) fp16 pair (weights).  lo = fp16(x - float(hi)).
__global__ void __launch_bounds__(256) split_f16(
    const float* __restrict__ x, __half* __restrict__ hi,
    __half* __restrict__ lo, int n4)
{
    int i = blockIdx.x * 256 + threadIdx.x;
    if (i >= n4) return;
    float4 v = ((const float4*)x)[i];
    uint32_t h0 = pack_h2(v.x, v.y);
    uint32_t h1 = pack_h2(v.z, v.w);
    float2 f0 = h2_f2(h0), f1 = h2_f2(h1);
    ((uint2*)hi)[i] = make_uint2(h0, h1);
    ((uint2*)lo)[i] = make_uint2(pack_h2(v.x - f0.x, v.y - f0.y),
                                 pack_h2(v.z - f1.x, v.w - f1.y));
}

// ---------------------------------------------------------------------------
// fp16 2-term GEMM:  C[M,N] = A[M,K] @ W[N,K]^T ≈ Ah·Wh + Ah·Wl
// CTA 128x128, BK=32, 8 warps (2x4, warp 64x32), 3-stage cp.async pipeline,
// 2 CTAs/SM. Rows padded to 80 B (conflict-free ldmatrix).
// EPI=0: fp32 C.  EPI=1: fp16 hi+lo.  EPI=2: fp16 hi only.
// ---------------------------------------------------------------------------
#define G2_ROWB  80
#define G2_TILE  (128 * G2_ROWB)     // 10240
#define G2_STAGE (3 * G2_TILE)       // 30720 (A, Wh, Wl)
#define G2_SMEM  (3 * G2_STAGE)      // 92160

__device__ __forceinline__ void g2_load(
    uint32_t smb, int stage, const __half* __restrict__ A,
    const __half* __restrict__ Wh, const __half* __restrict__ Wl,
    int m0, int n0, int k0, int K, int tid)
{
    const __half* srcs[3] = {A + (size_t)m0 * K + k0,
                             Wh + (size_t)n0 * K + k0,
                             Wl + (size_t)n0 * K + k0};
    #pragma unroll
    for (int t = 0; t < 3; t++) {
        #pragma unroll
        for (int i = 0; i < 2; i++) {
            int v = i * 256 + tid;
            int r = v >> 2;
            int c = (v & 3) * 16;
            cp16(smb + stage * G2_STAGE + t * G2_TILE + r * G2_ROWB + c,
                 (const char*)srcs[t] + (size_t)r * K * 2 + c);
        }
    }
}

template <int EPI>
__global__ void __launch_bounds__(256, 2) gemm_f16(
    const __half* __restrict__ A, const __half* __restrict__ Wh,
    const __half* __restrict__ Wl, float* __restrict__ C,
    __half* __restrict__ Chi, __half* __restrict__ Clo, int M, int N, int K)
{
    extern __shared__ __align__(128) char sm[];
    const uint32_t smb = smem_u32(sm);
    const int tid  = threadIdx.x;
    const int wid  = tid >> 5;
    const int lane = tid & 31;
    const int wm = wid >> 2;
    const int wn = wid & 3;
    const int m0 = blockIdx.y * 128;
    const int n0 = blockIdx.x * 128;

    float acc[4][4][4];
    #pragma unroll
    for (int i = 0; i < 4; i++)
        #pragma unroll
        for (int j = 0; j < 4; j++)
            #pragma unroll
            for (int e = 0; e < 4; e++) acc[i][j][e] = 0.0f;

    const int a_row = wm * 64 + (lane & 15);
    const int a_cb  = ((lane >> 4) & 1) * 16;
    const int b_row = wn * 32 + (lane & 7) + ((lane >> 4) << 3);
    const int b_cb  = ((lane >> 3) & 1) * 16;

    const int nchunks = K / 32;
    g2_load(smb, 0, A, Wh, Wl, m0, n0, 0, K, tid);
    CP_COMMIT;
    g2_load(smb, 1, A, Wh, Wl, m0, n0, 32, K, tid);
    CP_COMMIT;

    for (int c = 0; c < nchunks; c++) {
        CP_WAIT1;            // chunk c's stage resident
        __syncthreads();     // all warps done with stage (c-1)%3 == (c+2)%3
        if (c + 2 < nchunks)
            g2_load(smb, (c + 2) % 3, A, Wh, Wl, m0, n0, (c + 2) * 32, K, tid);
        CP_COMMIT;           // empty group when skipped (keeps count invariant)

        const uint32_t st = smb + (c % 3) * G2_STAGE;
        #pragma unroll
        for (int kk = 0; kk < 2; kk++) {
            const int kb = kk * 32;
            uint32_t bh[4][2], bl[4][2];
            #pragma unroll
            for (int nt2 = 0; nt2 < 2; nt2++) {
                uint32_t r4[4];
                uint32_t baddr = st + G2_TILE +
                                 (b_row + nt2 * 16) * G2_ROWB + kb + b_cb;
                ldsm4(r4, baddr);
                bh[nt2 * 2][0] = r4[0]; bh[nt2 * 2][1] = r4[1];
                bh[nt2 * 2 + 1][0] = r4[2]; bh[nt2 * 2 + 1][1] = r4[3];
                ldsm4(r4, baddr + G2_TILE);
                bl[nt2 * 2][0] = r4[0]; bl[nt2 * 2][1] = r4[1];
                bl[nt2 * 2 + 1][0] = r4[2]; bl[nt2 * 2 + 1][1] = r4[3];
            }
            #pragma unroll
            for (int mt = 0; mt < 4; mt++) {
                uint32_t ah[4];
                ldsm4(ah, st + (a_row + mt * 16) * G2_ROWB + kb + a_cb);
                #pragma unroll
                for (int nt = 0; nt < 4; nt++) {
                    mma_f16(acc[mt][nt], ah, bh[nt]);
                    mma_f16(acc[mt][nt], ah, bl[nt]);
                }
            }
        }
    }

    #pragma unroll
    for (int mt = 0; mt < 4; mt++) {
        const int row = m0 + wm * 64 + mt * 16 + (lane >> 2);
        #pragma unroll
        for (int nt = 0; nt < 4; nt++) {
            const int col = n0 + wn * 32 + nt * 8 + (lane & 3) * 2;
            float a0 = acc[mt][nt][0], a1 = acc[mt][nt][1];
            float a2 = acc[mt][nt][2], a3 = acc[mt][nt][3];
            if (EPI == 0) {
                *(float2*)&C[(size_t)row * N + col] = make_float2(a0, a1);
                *(float2*)&C[(size_t)(row + 8) * N + col] = make_float2(a2, a3);
            } else {
                uint32_t h0 = pack_h2(a0, a1);
                uint32_t h1 = pack_h2(a2, a3);
                *(uint32_t*)&Chi[(size_t)row * N + col] = h0;
                *(uint32_t*)&Chi[(size_t)(row + 8) * N + col] = h1;
                if (EPI == 1) {
                    float2 f0 = h2_f2(h0), f1 = h2_f2(h1);
                    *(uint32_t*)&Clo[(size_t)row * N + col] =
                        pack_h2(a0 - f0.x, a1 - f0.y);
                    *(uint32_t*)&Clo[(size_t)(row + 8) * N + col] =
                        pack_h2(a2 - f1.x, a3 - f1.y);
                }
            }
        }
    }
}

// ---------------------------------------------------------------------------
// Flash attention, fp16 HMMA, double-buffered KV.
// BQ=128, BKV=64. Q hi-only; K,V hi+lo (2-term MMAs: X·(Yh+Yl)).
// 8 warps; warp w owns Q rows [w*16, w*16+16).
// ---------------------------------------------------------------------------
#define FROWB 272
#define FQ    0
#define FSTG0 (128 * FROWB)               // 34816 (end of Q)
#define FSTG  (4 * 64 * FROWB)            // 69632 per KV stage
#define FKH   0
#define FKL   (64 * FROWB)
#define FVH   (2 * 64 * FROWB)
#define FVL   (3 * 64 * FROWB)
#define FMSK  (FSTG0 + 2 * FSTG)          // 174080
#define FSMEM (FMSK + 512)                // 174592

__device__ __forceinline__ void fl_loadkv(
    uint32_t smb, int stg, const __half* __restrict__ kh,
    const __half* __restrict__ kl, const __half* __restrict__ vh,
    const __half* __restrict__ vl, const int* __restrict__ amask,
    int b, int h, int kt, int tid)
{
    const uint32_t base = smb + FSTG0 + stg * FSTG;
    const size_t krow0 = (size_t)b * SEQ + (size_t)kt * 64;
    #pragma unroll
    for (int i = 0; i < 4; i++) {
        int idx = i * 256 + tid;
        int r = idx >> 4;
        int c = (idx & 15) * 16;
        size_t go = ((krow0 + r) * DMODEL + h * HDIM) * 2 + c;
        cp16(base + FKH + r * FROWB + c, (const char*)kh + go);
        cp16(base + FKL + r * FROWB + c, (const char*)kl + go);
        cp16(base + FVH + r * FROWB + c, (const char*)vh + go);
        cp16(base + FVL + r * FROWB + c, (const char*)vl + go);
    }
    if (tid < 16)
        cp16(smb + FMSK + stg * 256 + tid * 16,
             (const char*)(amask + b * SEQ + kt * 64) + tid * 16);
}

__global__ void __launch_bounds__(256) flash_f16(
    const __half* __restrict__ qh, const __half* __restrict__ kh,
    const __half* __restrict__ kl, const __half* __restrict__ vh,
    const __half* __restrict__ vl, const int* __restrict__ amask,
    __half* __restrict__ chi)
{
    extern __shared__ __align__(128) char sm[];
    const uint32_t smb = smem_u32(sm);

    const int b  = blockIdx.z;
    const int h  = blockIdx.y;
    const int qt = (int)gridDim.x - 1 - (int)blockIdx.x;   // heavy tiles first
    const int tid = threadIdx.x;
    const int wid = tid >> 5;
    const int lane = tid & 31;

    const size_t qrow0 = (size_t)b * SEQ + (size_t)qt * 128;

    // Q hi tile
    #pragma unroll
    for (int i = 0; i < 8; i++) {
        int idx = i * 256 + tid;
        int r = idx >> 4;
        int c = (idx & 15) * 16;
        size_t go = ((qrow0 + r) * DMODEL + h * HDIM) * 2 + c;
        cp16(smb + FQ + r * FROWB + c, (const char*)qh + go);
    }
    fl_loadkv(smb, 0, kh, kl, vh, vl, amask, b, h, 0, tid);
    CP_COMMIT;

    float o[16][4];
    #pragma unroll
    for (int nt = 0; nt < 16; nt++)
        #pragma unroll
        for (int e = 0; e < 4; e++) o[nt][e] = 0.0f;
    float mA = -1e30f, mB = -1e30f, lA = 0.0f, lB = 0.0f;

    const float scale = 0.08838834764831843f;   // 1/sqrt(128)
    const int rA = lane >> 2;
    const int growA = qt * 128 + wid * 16 + rA;
    const int growB = growA + 8;
    const int ktmax = 2 * qt + 1;

    for (int kt = 0; kt <= ktmax; kt++) {
        CP_WAIT0;
        __syncthreads();     // stage (kt+1)&1 free (all warps done with kt-1)
        if (kt < ktmax)
            fl_loadkv(smb, (kt + 1) & 1, kh, kl, vh, vl, amask, b, h, kt + 1, tid);
        CP_COMMIT;

        const int stg = kt & 1;
        const uint32_t kvb = smb + FSTG0 + stg * FSTG;
        const int* Ms = (const int*)(sm + FMSK + stg * 256);

        // ---- S = Q (Kh+Kl)^T ----
        float s[8][4];
        #pragma unroll
        for (int nt = 0; nt < 8; nt++)
            #pragma unroll
            for (int e = 0; e < 4; e++) s[nt][e] = 0.0f;

        #pragma unroll
        for (int kk = 0; kk < 8; kk++) {
            uint32_t qf[4];
            ldsm4(qf, smb + FQ + (wid * 16 + (lane & 15)) * FROWB +
                      kk * 32 + ((lane >> 4) & 1) * 16);
            #pragma unroll
            for (int g = 0; g < 4; g++) {
                uint32_t kf[4], lf[4];
                uint32_t baddr = kvb + FKH +
                                 (g * 16 + (lane & 7) + ((lane >> 4) << 3)) * FROWB +
                                 kk * 32 + ((lane >> 3) & 1) * 16;
                ldsm4(kf, baddr);
                ldsm4(lf, baddr + FKL);
                mma_f16(s[2 * g], qf, kf);
                mma_f16(s[2 * g], qf, lf);
                mma_f16(s[2 * g + 1], qf, kf + 2);
                mma_f16(s[2 * g + 1], qf, lf + 2);
            }
        }

        // ---- mask + scale + row max ----
        float tmaxA = -1e30f, tmaxB = -1e30f;
        #pragma unroll
        for (int nt = 0; nt < 8; nt++) {
            int lc = nt * 8 + (lane & 3) * 2;
            int gc = kt * 64 + lc;
            int mk0 = Ms[lc], mk1 = Ms[lc + 1];
            float v0 = s[nt][0] * scale; if (gc > growA || !mk0) v0 = -10000.0f;
            float v1 = s[nt][1] * scale; if (gc + 1 > growA || !mk1) v1 = -10000.0f;
            float v2 = s[nt][2] * scale; if (gc > growB || !mk0) v2 = -10000.0f;
            float v3 = s[nt][3] * scale; if (gc + 1 > growB || !mk1) v3 = -10000.0f;
            s[nt][0] = v0; s[nt][1] = v1; s[nt][2] = v2; s[nt][3] = v3;
            tmaxA = fmaxf(tmaxA, fmaxf(v0, v1));
            tmaxB = fmaxf(tmaxB, fmaxf(v2, v3));
        }
        tmaxA = fmaxf(tmaxA, __shfl_xor_sync(0xffffffffu, tmaxA, 1));
        tmaxA = fmaxf(tmaxA, __shfl_xor_sync(0xffffffffu, tmaxA, 2));
        tmaxB = fmaxf(tmaxB, __shfl_xor_sync(0xffffffffu, tmaxB, 1));
        tmaxB = fmaxf(tmaxB, __shfl_xor_sync(0xffffffffu, tmaxB, 2));

        float mAn = fmaxf(mA, tmaxA), mBn = fmaxf(mB, tmaxB);
        float aAl = __expf(mA - mAn), aBl = __expf(mB - mBn);

        // ---- P = exp(S - m) -> fp16 fragments ----
        uint32_t phi[8][2];
        float sumA = 0.0f, sumB = 0.0f;
        #pragma unroll
        for (int nt = 0; nt < 8; nt++) {
            float p0 = __expf(s[nt][0] - mAn), p1 = __expf(s[nt][1] - mAn);
            float p2 = __expf(s[nt][2] - mBn), p3 = __expf(s[nt][3] - mBn);
            sumA += p0 + p1; sumB += p2 + p3;
            phi[nt][0] = pack_h2(p0, p1);
            phi[nt][1] = pack_h2(p2, p3);
        }
        sumA += __shfl_xor_sync(0xffffffffu, sumA, 1);
        sumA += __shfl_xor_sync(0xffffffffu, sumA, 2);
        sumB += __shfl_xor_sync(0xffffffffu, sumB, 1);
        sumB += __shfl_xor_sync(0xffffffffu, sumB, 2);
        lA = lA * aAl + sumA;
        lB = lB * aBl + sumB;
        mA = mAn; mB = mBn;

        #pragma unroll
        for (int nt = 0; nt < 16; nt++) {
            o[nt][0] *= aAl; o[nt][1] *= aAl;
            o[nt][2] *= aBl; o[nt][3] *= aBl;
        }

        // ---- O += P (Vh+Vl) ----
        #pragma unroll
        for (int t = 0; t < 4; t++) {
            uint32_t ah[4] = {phi[2 * t][0], phi[2 * t][1],
                              phi[2 * t + 1][0], phi[2 * t + 1][1]};
            #pragma unroll
            for (int g = 0; g < 8; g++) {
                uint32_t vf[4], wf[4];
                uint32_t vaddr = kvb + FVH +
                                 (t * 16 + (lane & 7) + ((lane >> 3) & 1) * 8) * FROWB +
                                 g * 32 + (lane >> 4) * 16;
                ldsm4t(vf, vaddr);
                ldsm4t(wf, vaddr + (FVL - FVH));
                mma_f16(o[2 * g], ah, vf);
                mma_f16(o[2 * g], ah, wf);
                mma_f16(o[2 * g + 1], ah, vf + 2);
                mma_f16(o[2 * g + 1], ah, wf + 2);
            }
        }
    }

    // ---- normalize + store context (fp16 hi only) ----
    const float invA = 1.0f / lA, invB = 1.0f / lB;
    const size_t rgA = qrow0 + wid * 16 + rA;
    const size_t rgB = rgA + 8;
    #pragma unroll
    for (int nt = 0; nt < 16; nt++) {
        int col = h * HDIM + nt * 8 + (lane & 3) * 2;
        *(uint32_t*)&chi[rgA * DMODEL + col] =
            pack_h2(o[nt][0] * invA, o[nt][1] * invA);
        *(uint32_t*)&chi[rgB * DMODEL + col] =
            pack_h2(o[nt][2] * invB, o[nt][3] * invB);
    }
}

// ---------------------------------------------------------------------------
// Launch (ordered so ncu -s 5 -c 1 captures the first GEMM)
// ---------------------------------------------------------------------------
extern "C" void kernel_launch(void* const* d_in, const int* in_sizes, int n_in,
                              void* d_out, int out_size)
{
    const float* query = (const float*)d_in[0];
    const float* key   = (const float*)d_in[1];
    const float* value = (const float*)d_in[2];
    const int*   amask = (const int*)  d_in[3];
    const float* Wq    = (const float*)d_in[4];
    const float* Wk    = (const float*)d_in[5];
    const float* Wv    = (const float*)d_in[6];
    const float* Wo    = (const float*)d_in[7];
    float* out = (float*)d_out;

    __half *xq, *xk, *xv, *wqh, *wql, *wkh, *wkl, *wvh, *wvl, *woh, *wol;
    __half *qh, *khb, *klb, *vhb, *vlb, *chb;
    cudaGetSymbolAddress((void**)&xq,  g_Xq);
    cudaGetSymbolAddress((void**)&xk,  g_Xk);
    cudaGetSymbolAddress((void**)&xv,  g_Xv);
    cudaGetSymbolAddress((void**)&wqh, g_Wqh);
    cudaGetSymbolAddress((void**)&wql, g_Wql);
    cudaGetSymbolAddress((void**)&wkh, g_Wkh);
    cudaGetSymbolAddress((void**)&wkl, g_Wkl);
    cudaGetSymbolAddress((void**)&wvh, g_Wvh);
    cudaGetSymbolAddress((void**)&wvl, g_Wvl);
    cudaGetSymbolAddress((void**)&woh, g_Woh);
    cudaGetSymbolAddress((void**)&wol, g_Wol);
    cudaGetSymbolAddress((void**)&qh,  g_Qh);
    cudaGetSymbolAddress((void**)&khb, g_Kh);
    cudaGetSymbolAddress((void**)&klb, g_Kl);
    cudaGetSymbolAddress((void**)&vhb, g_Vh);
    cudaGetSymbolAddress((void**)&vlb, g_Vl);
    cudaGetSymbolAddress((void**)&chb, g_Ch);

    cudaFuncSetAttribute(gemm_f16<0>,
                         cudaFuncAttributeMaxDynamicSharedMemorySize, G2_SMEM);
    cudaFuncSetAttribute(gemm_f16<1>,
                         cudaFuncAttributeMaxDynamicSharedMemorySize, G2_SMEM);
    cudaFuncSetAttribute(gemm_f16<2>,
                         cudaFuncAttributeMaxDynamicSharedMemorySize, G2_SMEM);
    cudaFuncSetAttribute(flash_f16,
                         cudaFuncAttributeMaxDynamicSharedMemorySize, FSMEM);

    const int nA4 = MROWS * DMODEL / 4;
    const int nW4 = DMODEL * DMODEL / 4;
    dim3 gg(DMODEL / 128, MROWS / 128);      // (16, 64)

    cvt_f16  <<<nA4 / 256, 256>>>(query, xq, nA4);                     // 1
    split_f16<<<nW4 / 256, 256>>>(Wq, wqh, wql, nW4);                  // 2
    cvt_f16  <<<nA4 / 256, 256>>>(key, xk, nA4);                       // 3
    split_f16<<<nW4 / 256, 256>>>(Wk, wkh, wkl, nW4);                  // 4
    cvt_f16  <<<nA4 / 256, 256>>>(value, xv, nA4);                     // 5
    gemm_f16<2><<<gg, 256, G2_SMEM>>>(xq, wqh, wql, nullptr, qh, nullptr,
                                      MROWS, DMODEL, DMODEL);          // 6 (ncu)
    split_f16<<<nW4 / 256, 256>>>(Wv, wvh, wvl, nW4);                  // 7
    gemm_f16<1><<<gg, 256, G2_SMEM>>>(xk, wkh, wkl, nullptr, khb, klb,
                                      MROWS, DMODEL, DMODEL);          // 8
    gemm_f16<1><<<gg, 256, G2_SMEM>>>(xv, wvh, wvl, nullptr, vhb, vlb,
                                      MROWS, DMODEL, DMODEL);          // 9
    flash_f16<<<dim3(SEQ / 128, NHEAD, BATCH), 256, FSMEM>>>(
        qh, khb, klb, vhb, vlb, amask, chb);                           // 10
    split_f16<<<nW4 / 256, 256>>>(Wo, woh, wol, nW4);                  // 11
    gemm_f16<0><<<gg, 256, G2_SMEM>>>(chb, woh, wol, out, nullptr, nullptr,
                                      MROWS, DMODEL, DMODEL);          // 12
}

// round 6
// speedup vs baseline: 7.4255x; 1.0264x over previous
#include <cuda_runtime.h>
#include <cuda_fp16.h>
#include <cstdint>

// Problem constants
#define BATCH 4
#define SEQ   2048
#define DMODEL 2048
#define NHEAD 16
#define HDIM  128
#define MROWS (BATCH * SEQ)   // 8192

// ---------------------------------------------------------------------------
// Scratch (device globals; allocation in kernel_launch is forbidden)
// ---------------------------------------------------------------------------
__device__ __half g_Xq[(size_t)MROWS * DMODEL];
__device__ __half g_Xk[(size_t)MROWS * DMODEL];
__device__ __half g_Xv[(size_t)MROWS * DMODEL];
__device__ __half g_Wqh[(size_t)DMODEL * DMODEL];
__device__ __half g_Wql[(size_t)DMODEL * DMODEL];
__device__ __half g_Wkh[(size_t)DMODEL * DMODEL];
__device__ __half g_Wkl[(size_t)DMODEL * DMODEL];
__device__ __half g_Wvh[(size_t)DMODEL * DMODEL];
__device__ __half g_Wvl[(size_t)DMODEL * DMODEL];
__device__ __half g_Woh[(size_t)DMODEL * DMODEL];
__device__ __half g_Wol[(size_t)DMODEL * DMODEL];
__device__ __half g_Qh[(size_t)MROWS * DMODEL];
__device__ __half g_Kh[(size_t)MROWS * DMODEL];
__device__ __half g_Kl[(size_t)MROWS * DMODEL];
__device__ __half g_Vh[(size_t)MROWS * DMODEL];
__device__ __half g_Vl[(size_t)MROWS * DMODEL];
__device__ __half g_Ch[(size_t)MROWS * DMODEL];

// ---------------------------------------------------------------------------
// PTX helpers (sm_80-level: mma.sync / ldmatrix / cp.async)
// ---------------------------------------------------------------------------
__device__ __forceinline__ uint32_t smem_u32(const void* p) {
    uint32_t a;
    asm("{ .reg .u64 t; cvta.to.shared.u64 t, %1; cvt.u32.u64 %0, t; }"
        : "=r"(a) : "l"(p));
    return a;
}
__device__ __forceinline__ void ldsm4(uint32_t* r, uint32_t addr) {
    asm volatile("ldmatrix.sync.aligned.m8n8.x4.shared.b16 {%0,%1,%2,%3}, [%4];"
                 : "=r"(r[0]), "=r"(r[1]), "=r"(r[2]), "=r"(r[3]) : "r"(addr));
}
__device__ __forceinline__ void ldsm4t(uint32_t* r, uint32_t addr) {
    asm volatile("ldmatrix.sync.aligned.m8n8.x4.trans.shared.b16 {%0,%1,%2,%3}, [%4];"
                 : "=r"(r[0]), "=r"(r[1]), "=r"(r[2]), "=r"(r[3]) : "r"(addr));
}
__device__ __forceinline__ void mma_f16(float* d, const uint32_t* a,
                                        const uint32_t* b) {
    asm volatile(
        "mma.sync.aligned.m16n8k16.row.col.f32.f16.f16.f32 "
        "{%0,%1,%2,%3}, {%4,%5,%6,%7}, {%8,%9}, {%0,%1,%2,%3};"
        : "+f"(d[0]), "+f"(d[1]), "+f"(d[2]), "+f"(d[3])
        : "r"(a[0]), "r"(a[1]), "r"(a[2]), "r"(a[3]), "r"(b[0]), "r"(b[1]));
}
__device__ __forceinline__ void cp16(uint32_t dst, const void* src) {
    asm volatile("cp.async.cg.shared.global [%0], [%1], 16;"
                 :: "r"(dst), "l"(src) : "memory");
}
#define CP_COMMIT asm volatile("cp.async.commit_group;" ::: "memory")
#define CP_WAIT0  asm volatile("cp.async.wait_group 0;" ::: "memory")
#define CP_WAIT1  asm volatile("cp.async.wait_group 1;" ::: "memory")

// pack two fp32 -> half2 (first arg -> low half)
__device__ __forceinline__ uint32_t pack_h2(float lo, float hi) {
    uint32_t r;
    asm("cvt.rn.f16x2.f32 %0, %1, %2;" : "=r"(r) : "f"(hi), "f"(lo));
    return r;
}
__device__ __forceinline__ float2 h2_f2(uint32_t u) {
    __half2 h = *reinterpret_cast<__half2*>(&u);
    return __half22float2(h);
}

// ---------------------------------------------------------------------------
// Fused converts: q,k,v fp32 -> fp16 (hi only), one launch
// ---------------------------------------------------------------------------
#define NA4 (MROWS * DMODEL / 4)
#define NW4 (DMODEL * DMODEL / 4)

__global__ void __launch_bounds__(256) cvt3_f16(
    const float* __restrict__ x0, const float* __restrict__ x1,
    const float* __restrict__ x2, __half* __restrict__ h0,
    __half* __restrict__ h1, __half* __restrict__ h2)
{
    int i = blockIdx.x * 256 + threadIdx.x;
    int which = i / NA4;
    int j = i - which * NA4;
    const float* x = (which == 0) ? x0 : (which == 1) ? x1 : x2;
    __half* h = (which == 0) ? h0 : (which == 1) ? h1 : h2;
    float4 v = ((const float4*)x)[j];
    ((uint2*)h)[j] = make_uint2(pack_h2(v.x, v.y), pack_h2(v.z, v.w));
}

// Fused weight splits: 4 matrices fp32 -> (hi, lo) fp16, one launch
__global__ void __launch_bounds__(256) split4_f16(
    const float* __restrict__ w0, const float* __restrict__ w1,
    const float* __restrict__ w2, const float* __restrict__ w3,
    __half* __restrict__ h0, __half* __restrict__ l0,
    __half* __restrict__ h1, __half* __restrict__ l1,
    __half* __restrict__ h2, __half* __restrict__ l2,
    __half* __restrict__ h3, __half* __restrict__ l3)
{
    int i = blockIdx.x * 256 + threadIdx.x;
    int which = i / NW4;
    int j = i - which * NW4;
    const float* x = (which == 0) ? w0 : (which == 1) ? w1
                     : (which == 2) ? w2 : w3;
    __half* hi = (which == 0) ? h0 : (which == 1) ? h1
                 : (which == 2) ? h2 : h3;
    __half* lo = (which == 0) ? l0 : (which == 1) ? l1
                 : (which == 2) ? l2 : l3;
    float4 v = ((const float4*)x)[j];
    uint32_t a0 = pack_h2(v.x, v.y);
    uint32_t a1 = pack_h2(v.z, v.w);
    float2 f0 = h2_f2(a0), f1 = h2_f2(a1);
    ((uint2*)hi)[j] = make_uint2(a0, a1);
    ((uint2*)lo)[j] = make_uint2(pack_h2(v.x - f0.x, v.y - f0.y),
                                 pack_h2(v.z - f1.x, v.w - f1.y));
}

// ---------------------------------------------------------------------------
// fp16 2-term GEMM core:  C[128,128 tile] = A @ W^T ≈ Ah·Wh + Ah·Wl
// BK=32, 8 warps (2x4, warp 64x32), 3-stage cp.async pipeline, 2 CTAs/SM.
// ---------------------------------------------------------------------------
#define G2_ROWB  80
#define G2_TILE  (128 * G2_ROWB)     // 10240
#define G2_STAGE (3 * G2_TILE)       // 30720 (A, Wh, Wl)
#define G2_SMEM  (3 * G2_STAGE)      // 92160

__device__ __forceinline__ void g2_load(
    uint32_t smb, int stage, const __half* __restrict__ A,
    const __half* __restrict__ Wh, const __half* __restrict__ Wl,
    int m0, int n0, int k0, int tid)
{
    const __half* srcs[3] = {A + (size_t)m0 * DMODEL + k0,
                             Wh + (size_t)n0 * DMODEL + k0,
                             Wl + (size_t)n0 * DMODEL + k0};
    #pragma unroll
    for (int t = 0; t < 3; t++) {
        #pragma unroll
        for (int i = 0; i < 2; i++) {
            int v = i * 256 + tid;
            int r = v >> 2;
            int c = (v & 3) * 16;
            cp16(smb + stage * G2_STAGE + t * G2_TILE + r * G2_ROWB + c,
                 (const char*)srcs[t] + (size_t)r * DMODEL * 2 + c);
        }
    }
}

// Main loop shared by both GEMM kernels; returns acc by reference.
__device__ __forceinline__ void g2_mainloop(
    uint32_t smb, const __half* __restrict__ A, const __half* __restrict__ Wh,
    const __half* __restrict__ Wl, int m0, int n0, int tid,
    float acc[4][4][4])
{
    const int lane = tid & 31;
    const int wid  = tid >> 5;
    const int wm = wid >> 2;
    const int wn = wid & 3;
    const int a_row = wm * 64 + (lane & 15);
    const int a_cb  = ((lane >> 4) & 1) * 16;
    const int b_row = wn * 32 + (lane & 7) + ((lane >> 4) << 3);
    const int b_cb  = ((lane >> 3) & 1) * 16;

    const int nchunks = DMODEL / 32;   // 64
    g2_load(smb, 0, A, Wh, Wl, m0, n0, 0, tid);
    CP_COMMIT;
    g2_load(smb, 1, A, Wh, Wl, m0, n0, 32, tid);
    CP_COMMIT;

    for (int c = 0; c < nchunks; c++) {
        CP_WAIT1;
        __syncthreads();
        if (c + 2 < nchunks)
            g2_load(smb, (c + 2) % 3, A, Wh, Wl, m0, n0, (c + 2) * 32, tid);
        CP_COMMIT;

        const uint32_t st = smb + (c % 3) * G2_STAGE;
        #pragma unroll
        for (int kk = 0; kk < 2; kk++) {
            const int kb = kk * 32;
            uint32_t bh[4][2], bl[4][2];
            #pragma unroll
            for (int nt2 = 0; nt2 < 2; nt2++) {
                uint32_t r4[4];
                uint32_t baddr = st + G2_TILE +
                                 (b_row + nt2 * 16) * G2_ROWB + kb + b_cb;
                ldsm4(r4, baddr);
                bh[nt2 * 2][0] = r4[0]; bh[nt2 * 2][1] = r4[1];
                bh[nt2 * 2 + 1][0] = r4[2]; bh[nt2 * 2 + 1][1] = r4[3];
                ldsm4(r4, baddr + G2_TILE);
                bl[nt2 * 2][0] = r4[0]; bl[nt2 * 2][1] = r4[1];
                bl[nt2 * 2 + 1][0] = r4[2]; bl[nt2 * 2 + 1][1] = r4[3];
            }
            #pragma unroll
            for (int mt = 0; mt < 4; mt++) {
                uint32_t ah[4];
                ldsm4(ah, st + (a_row + mt * 16) * G2_ROWB + kb + a_cb);
                #pragma unroll
                for (int nt = 0; nt < 4; nt++) {
                    mma_f16(acc[mt][nt], ah, bh[nt]);
                    mma_f16(acc[mt][nt], ah, bl[nt]);
                }
            }
        }
    }
}

// Fused Q/K/V projection GEMM: 3072 tiles in one launch (tail amortized).
// which = tile/1024: 0 -> Q (hi out), 1 -> K (hi+lo), 2 -> V (hi+lo).
__global__ void __launch_bounds__(256, 2) gemm_qkv(
    const __half* __restrict__ xq, const __half* __restrict__ xk,
    const __half* __restrict__ xv,
    const __half* __restrict__ wqh, const __half* __restrict__ wql,
    const __half* __restrict__ wkh, const __half* __restrict__ wkl,
    const __half* __restrict__ wvh, const __half* __restrict__ wvl,
    __half* __restrict__ qh, __half* __restrict__ kh, __half* __restrict__ kl,
    __half* __restrict__ vh, __half* __restrict__ vl)
{
    extern __shared__ __align__(128) char sm[];
    const uint32_t smb = smem_u32(sm);
    const int t = blockIdx.x;
    const int which = t >> 10;
    const int idx = t & 1023;
    const int m0 = (idx >> 4) * 128;
    const int n0 = (idx & 15) * 128;
    const int tid = threadIdx.x;

    const __half* A  = (which == 0) ? xq  : (which == 1) ? xk  : xv;
    const __half* Wh = (which == 0) ? wqh : (which == 1) ? wkh : wvh;
    const __half* Wl = (which == 0) ? wql : (which == 1) ? wkl : wvl;
    __half* Oh = (which == 0) ? qh : (which == 1) ? kh : vh;
    __half* Ol = (which == 1) ? kl : vl;   // unused for which==0

    float acc[4][4][4];
    #pragma unroll
    for (int i = 0; i < 4; i++)
        #pragma unroll
        for (int j = 0; j < 4; j++)
            #pragma unroll
            for (int e = 0; e < 4; e++) acc[i][j][e] = 0.0f;

    g2_mainloop(smb, A, Wh, Wl, m0, n0, tid, acc);

    const int lane = tid & 31;
    const int wid  = tid >> 5;
    #pragma unroll
    for (int mt = 0; mt < 4; mt++) {
        const int row = m0 + (wid >> 2) * 64 + mt * 16 + (lane >> 2);
        #pragma unroll
        for (int nt = 0; nt < 4; nt++) {
            const int col = n0 + (wid & 3) * 32 + nt * 8 + (lane & 3) * 2;
            float a0 = acc[mt][nt][0], a1 = acc[mt][nt][1];
            float a2 = acc[mt][nt][2], a3 = acc[mt][nt][3];
            uint32_t h0 = pack_h2(a0, a1);
            uint32_t h1 = pack_h2(a2, a3);
            *(uint32_t*)&Oh[(size_t)row * DMODEL + col] = h0;
            *(uint32_t*)&Oh[(size_t)(row + 8) * DMODEL + col] = h1;
            if (which != 0) {
                float2 f0 = h2_f2(h0), f1 = h2_f2(h1);
                *(uint32_t*)&Ol[(size_t)row * DMODEL + col] =
                    pack_h2(a0 - f0.x, a1 - f0.y);
                *(uint32_t*)&Ol[(size_t)(row + 8) * DMODEL + col] =
                    pack_h2(a2 - f1.x, a3 - f1.y);
            }
        }
    }
}

// Output projection GEMM: fp32 result to d_out.
__global__ void __launch_bounds__(256, 2) gemm_out(
    const __half* __restrict__ A, const __half* __restrict__ Wh,
    const __half* __restrict__ Wl, float* __restrict__ C)
{
    extern __shared__ __align__(128) char sm[];
    const uint32_t smb = smem_u32(sm);
    const int m0 = blockIdx.y * 128;
    const int n0 = blockIdx.x * 128;
    const int tid = threadIdx.x;

    float acc[4][4][4];
    #pragma unroll
    for (int i = 0; i < 4; i++)
        #pragma unroll
        for (int j = 0; j < 4; j++)
            #pragma unroll
            for (int e = 0; e < 4; e++) acc[i][j][e] = 0.0f;

    g2_mainloop(smb, A, Wh, Wl, m0, n0, tid, acc);

    const int lane = tid & 31;
    const int wid  = tid >> 5;
    #pragma unroll
    for (int mt = 0; mt < 4; mt++) {
        const int row = m0 + (wid >> 2) * 64 + mt * 16 + (lane >> 2);
        #pragma unroll
        for (int nt = 0; nt < 4; nt++) {
            const int col = n0 + (wid & 3) * 32 + nt * 8 + (lane & 3) * 2;
            *(float2*)&C[(size_t)row * DMODEL + col] =
                make_float2(acc[mt][nt][0], acc[mt][nt][1]);
            *(float2*)&C[(size_t)(row + 8) * DMODEL + col] =
                make_float2(acc[mt][nt][2], acc[mt][nt][3]);
        }
    }
}

// ---------------------------------------------------------------------------
// Flash attention, fp16 HMMA, double-buffered KV, Q fragments in registers.
// BQ=128, BKV=64. Q hi-only; K,V hi+lo (2-term MMAs).
// ---------------------------------------------------------------------------
#define FROWB 272
#define FQ    0
#define FSTG0 (128 * FROWB)               // 34816
#define FSTG  (4 * 64 * FROWB)            // 69632 per KV stage
#define FKH   0
#define FKL   (64 * FROWB)
#define FVH   (2 * 64 * FROWB)
#define FVL   (3 * 64 * FROWB)
#define FMSK  (FSTG0 + 2 * FSTG)          // 174080
#define FSMEM (FMSK + 512)                // 174592

__device__ __forceinline__ void fl_loadkv(
    uint32_t smb, int stg, const __half* __restrict__ kh,
    const __half* __restrict__ kl, const __half* __restrict__ vh,
    const __half* __restrict__ vl, const int* __restrict__ amask,
    int b, int h, int kt, int tid)
{
    const uint32_t base = smb + FSTG0 + stg * FSTG;
    const size_t krow0 = (size_t)b * SEQ + (size_t)kt * 64;
    #pragma unroll
    for (int i = 0; i < 4; i++) {
        int idx = i * 256 + tid;
        int r = idx >> 4;
        int c = (idx & 15) * 16;
        size_t go = ((krow0 + r) * DMODEL + h * HDIM) * 2 + c;
        cp16(base + FKH + r * FROWB + c, (const char*)kh + go);
        cp16(base + FKL + r * FROWB + c, (const char*)kl + go);
        cp16(base + FVH + r * FROWB + c, (const char*)vh + go);
        cp16(base + FVL + r * FROWB + c, (const char*)vl + go);
    }
    if (tid < 16)
        cp16(smb + FMSK + stg * 256 + tid * 16,
             (const char*)(amask + b * SEQ + kt * 64) + tid * 16);
}

__global__ void __launch_bounds__(256) flash_f16(
    const __half* __restrict__ qh, const __half* __restrict__ kh,
    const __half* __restrict__ kl, const __half* __restrict__ vh,
    const __half* __restrict__ vl, const int* __restrict__ amask,
    __half* __restrict__ chi)
{
    extern __shared__ __align__(128) char sm[];
    const uint32_t smb = smem_u32(sm);

    const int b  = blockIdx.z;
    const int h  = blockIdx.y;
    const int qt = (int)gridDim.x - 1 - (int)blockIdx.x;   // heavy tiles first
    const int tid = threadIdx.x;
    const int wid = tid >> 5;
    const int lane = tid & 31;

    const size_t qrow0 = (size_t)b * SEQ + (size_t)qt * 128;

    // Q hi tile -> smem (read once into registers after first wait)
    #pragma unroll
    for (int i = 0; i < 8; i++) {
        int idx = i * 256 + tid;
        int r = idx >> 4;
        int c = (idx & 15) * 16;
        size_t go = ((qrow0 + r) * DMODEL + h * HDIM) * 2 + c;
        cp16(smb + FQ + r * FROWB + c, (const char*)qh + go);
    }
    fl_loadkv(smb, 0, kh, kl, vh, vl, amask, b, h, 0, tid);
    CP_COMMIT;

    float o[16][4];
    #pragma unroll
    for (int nt = 0; nt < 16; nt++)
        #pragma unroll
        for (int e = 0; e < 4; e++) o[nt][e] = 0.0f;
    float mA = -1e30f, mB = -1e30f, lA = 0.0f, lB = 0.0f;
    uint32_t qf[8][4];   // Q fragments, loaded once

    const float scale = 0.08838834764831843f;   // 1/sqrt(128)
    const int rA = lane >> 2;
    const int growA = qt * 128 + wid * 16 + rA;
    const int growB = growA + 8;
    const int ktmax = 2 * qt + 1;
    const uint32_t qbase = smb + FQ + (wid * 16 + (lane & 15)) * FROWB +
                           ((lane >> 4) & 1) * 16;
    const uint32_t kbase0 = ((lane & 7) + ((lane >> 4) << 3)) * FROWB +
                            ((lane >> 3) & 1) * 16;
    const uint32_t vbase0 = ((lane & 7) + ((lane >> 3) & 1) * 8) * FROWB +
                            (lane >> 4) * 16;

    for (int kt = 0; kt <= ktmax; kt++) {
        CP_WAIT0;
        __syncthreads();
        if (kt == 0) {
            #pragma unroll
            for (int kk = 0; kk < 8; kk++) ldsm4(qf[kk], qbase + kk * 32);
        }
        if (kt < ktmax)
            fl_loadkv(smb, (kt + 1) & 1, kh, kl, vh, vl, amask, b, h, kt + 1, tid);
        CP_COMMIT;

        const int stg = kt & 1;
        const uint32_t kvb = smb + FSTG0 + stg * FSTG;
        const int* Ms = (const int*)(sm + FMSK + stg * 256);

        // ---- S = Q (Kh+Kl)^T ----
        float s[8][4];
        #pragma unroll
        for (int nt = 0; nt < 8; nt++)
            #pragma unroll
            for (int e = 0; e < 4; e++) s[nt][e] = 0.0f;

        #pragma unroll
        for (int kk = 0; kk < 8; kk++) {
            #pragma unroll
            for (int g = 0; g < 4; g++) {
                uint32_t kf[4], lf[4];
                uint32_t baddr = kvb + FKH + g * 16 * FROWB + kbase0 + kk * 32;
                ldsm4(kf, baddr);
                ldsm4(lf, baddr + FKL);
                mma_f16(s[2 * g], qf[kk], kf);
                mma_f16(s[2 * g], qf[kk], lf);
                mma_f16(s[2 * g + 1], qf[kk], kf + 2);
                mma_f16(s[2 * g + 1], qf[kk], lf + 2);
            }
        }

        // ---- mask + scale + row max ----
        float tmaxA = -1e30f, tmaxB = -1e30f;
        #pragma unroll
        for (int nt = 0; nt < 8; nt++) {
            int lc = nt * 8 + (lane & 3) * 2;
            int gc = kt * 64 + lc;
            int mk0 = Ms[lc], mk1 = Ms[lc + 1];
            float v0 = s[nt][0] * scale; if (gc > growA || !mk0) v0 = -10000.0f;
            float v1 = s[nt][1] * scale; if (gc + 1 > growA || !mk1) v1 = -10000.0f;
            float v2 = s[nt][2] * scale; if (gc > growB || !mk0) v2 = -10000.0f;
            float v3 = s[nt][3] * scale; if (gc + 1 > growB || !mk1) v3 = -10000.0f;
            s[nt][0] = v0; s[nt][1] = v1; s[nt][2] = v2; s[nt][3] = v3;
            tmaxA = fmaxf(tmaxA, fmaxf(v0, v1));
            tmaxB = fmaxf(tmaxB, fmaxf(v2, v3));
        }
        tmaxA = fmaxf(tmaxA, __shfl_xor_sync(0xffffffffu, tmaxA, 1));
        tmaxA = fmaxf(tmaxA, __shfl_xor_sync(0xffffffffu, tmaxA, 2));
        tmaxB = fmaxf(tmaxB, __shfl_xor_sync(0xffffffffu, tmaxB, 1));
        tmaxB = fmaxf(tmaxB, __shfl_xor_sync(0xffffffffu, tmaxB, 2));

        float mAn = fmaxf(mA, tmaxA), mBn = fmaxf(mB, tmaxB);
        float aAl = __expf(mA - mAn), aBl = __expf(mB - mBn);

        // ---- P = exp(S - m) -> fp16 fragments ----
        uint32_t phi[8][2];
        float sumA = 0.0f, sumB = 0.0f;
        #pragma unroll
        for (int nt = 0; nt < 8; nt++) {
            float p0 = __expf(s[nt][0] - mAn), p1 = __expf(s[nt][1] - mAn);
            float p2 = __expf(s[nt][2] - mBn), p3 = __expf(s[nt][3] - mBn);
            sumA += p0 + p1; sumB += p2 + p3;
            phi[nt][0] = pack_h2(p0, p1);
            phi[nt][1] = pack_h2(p2, p3);
        }
        sumA += __shfl_xor_sync(0xffffffffu, sumA, 1);
        sumA += __shfl_xor_sync(0xffffffffu, sumA, 2);
        sumB += __shfl_xor_sync(0xffffffffu, sumB, 1);
        sumB += __shfl_xor_sync(0xffffffffu, sumB, 2);
        lA = lA * aAl + sumA;
        lB = lB * aBl + sumB;
        mA = mAn; mB = mBn;

        #pragma unroll
        for (int nt = 0; nt < 16; nt++) {
            o[nt][0] *= aAl; o[nt][1] *= aAl;
            o[nt][2] *= aBl; o[nt][3] *= aBl;
        }

        // ---- O += P (Vh+Vl) ----
        #pragma unroll
        for (int t = 0; t < 4; t++) {
            uint32_t ah[4] = {phi[2 * t][0], phi[2 * t][1],
                              phi[2 * t + 1][0], phi[2 * t + 1][1]};
            #pragma unroll
            for (int g = 0; g < 8; g++) {
                uint32_t vf[4], wf[4];
                uint32_t vaddr = kvb + FVH + t * 16 * FROWB + vbase0 + g * 32;
                ldsm4t(vf, vaddr);
                ldsm4t(wf, vaddr + (FVL - FVH));
                mma_f16(o[2 * g], ah, vf);
                mma_f16(o[2 * g], ah, wf);
                mma_f16(o[2 * g + 1], ah, vf + 2);
                mma_f16(o[2 * g + 1], ah, wf + 2);
            }
        }
    }

    // ---- normalize + store context (fp16 hi only) ----
    const float invA = 1.0f / lA, invB = 1.0f / lB;
    const size_t rgA = qrow0 + wid * 16 + rA;
    const size_t rgB = rgA + 8;
    #pragma unroll
    for (int nt = 0; nt < 16; nt++) {
        int col = h * HDIM + nt * 8 + (lane & 3) * 2;
        *(uint32_t*)&chi[rgA * DMODEL + col] =
            pack_h2(o[nt][0] * invA, o[nt][1] * invA);
        *(uint32_t*)&chi[rgB * DMODEL + col] =
            pack_h2(o[nt][2] * invB, o[nt][3] * invB);
    }
}

// ---------------------------------------------------------------------------
// Launch: split4, cvt3, fused QKV GEMM, flash, out GEMM  (5 launches)
// ---------------------------------------------------------------------------
extern "C" void kernel_launch(void* const* d_in, const int* in_sizes, int n_in,
                              void* d_out, int out_size)
{
    const float* query = (const float*)d_in[0];
    const float* key   = (const float*)d_in[1];
    const float* value = (const float*)d_in[2];
    const int*   amask = (const int*)  d_in[3];
    const float* Wq    = (const float*)d_in[4];
    const float* Wk    = (const float*)d_in[5];
    const float* Wv    = (const float*)d_in[6];
    const float* Wo    = (const float*)d_in[7];
    float* out = (float*)d_out;

    __half *xq, *xk, *xv, *wqh, *wql, *wkh, *wkl, *wvh, *wvl, *woh, *wol;
    __half *qh, *khb, *klb, *vhb, *vlb, *chb;
    cudaGetSymbolAddress((void**)&xq,  g_Xq);
    cudaGetSymbolAddress((void**)&xk,  g_Xk);
    cudaGetSymbolAddress((void**)&xv,  g_Xv);
    cudaGetSymbolAddress((void**)&wqh, g_Wqh);
    cudaGetSymbolAddress((void**)&wql, g_Wql);
    cudaGetSymbolAddress((void**)&wkh, g_Wkh);
    cudaGetSymbolAddress((void**)&wkl, g_Wkl);
    cudaGetSymbolAddress((void**)&wvh, g_Wvh);
    cudaGetSymbolAddress((void**)&wvl, g_Wvl);
    cudaGetSymbolAddress((void**)&woh, g_Woh);
    cudaGetSymbolAddress((void**)&wol, g_Wol);
    cudaGetSymbolAddress((void**)&qh,  g_Qh);
    cudaGetSymbolAddress((void**)&khb, g_Kh);
    cudaGetSymbolAddress((void**)&klb, g_Kl);
    cudaGetSymbolAddress((void**)&vhb, g_Vh);
    cudaGetSymbolAddress((void**)&vlb, g_Vl);
    cudaGetSymbolAddress((void**)&chb, g_Ch);

    cudaFuncSetAttribute(gemm_qkv,
                         cudaFuncAttributeMaxDynamicSharedMemorySize, G2_SMEM);
    cudaFuncSetAttribute(gemm_out,
                         cudaFuncAttributeMaxDynamicSharedMemorySize, G2_SMEM);
    cudaFuncSetAttribute(flash_f16,
                         cudaFuncAttributeMaxDynamicSharedMemorySize, FSMEM);

    split4_f16<<<4 * NW4 / 256, 256>>>(Wq, Wk, Wv, Wo,
                                       wqh, wql, wkh, wkl, wvh, wvl, woh, wol);
    cvt3_f16<<<3 * NA4 / 256, 256>>>(query, key, value, xq, xk, xv);

    gemm_qkv<<<3072, 256, G2_SMEM>>>(xq, xk, xv, wqh, wql, wkh, wkl, wvh, wvl,
                                     qh, khb, klb, vhb, vlb);

    flash_f16<<<dim3(SEQ / 128, NHEAD, BATCH), 256, FSMEM>>>(
        qh, khb, klb, vhb, vlb, amask, chb);

    gemm_out<<<dim3(DMODEL / 128, MROWS / 128), 256, G2_SMEM>>>(chb, woh, wol, out);
}